// round 14
// baseline (speedup 1.0000x reference)
#include <cuda_runtime.h>
#include <cuda_fp16.h>
#include <cstdint>

// ---------------- problem constants ----------------
#define BW   64
#define NT   512
#define CC   192
#define HH   6
#define HD   32
#define NWIN 16
#define TBL  3375
#define KE2  384           // expanded K = 2*192 (fp16 hi|lo)

// ---------------- device scratch ----------------
__device__ float g_tbl[TBL * HH];
// bias/mask in mma-fragment layout: [h|w][iblk(8)][warp(4)][jt(8)][j(8)][lane(32)][4]
__device__ float g_biasF[HH * 8 * 4 * 8 * 8 * 32 * 4];      // 6.3 MB
__device__ float g_maskF[NWIN * 8 * 4 * 8 * 8 * 32 * 4];    // 16.8 MB
__device__ float g_q[BW * HH * NT * HD];
// k/v stored as fp16 hi only: 32 halfs (64B) per key
__device__ __half g_kE[(size_t)BW * HH * NT * 32];
__device__ __half g_vE[(size_t)BW * HH * NT * 32];
__device__ __half g_xE[(size_t)BW * NT * KE2];     // x expanded [hi|lo]
__device__ __half g_attE[(size_t)BW * NT * KE2];   // attn out expanded [hi|lo]
__device__ __half g_wqkvE[3 * CC * KE2];           // qkv_w expanded [hi|hi]
__device__ __half g_wprojE[CC * KE2];              // proj_w expanded [hi|hi]

#define SWZ(o) ((o) ^ (((o) >> 3) & 0x70))

__device__ __forceinline__ uint32_t s2u(const void* p) {
    return (uint32_t)__cvta_generic_to_shared(p);
}
__device__ __forceinline__ void ldsm4(uint32_t& r0, uint32_t& r1, uint32_t& r2, uint32_t& r3,
                                      uint32_t addr) {
    asm volatile("ldmatrix.sync.aligned.m8n8.x4.shared.b16 {%0,%1,%2,%3}, [%4];"
                 : "=r"(r0), "=r"(r1), "=r"(r2), "=r"(r3) : "r"(addr));
}
__device__ __forceinline__ void ldsm4t(uint32_t& r0, uint32_t& r1, uint32_t& r2, uint32_t& r3,
                                       uint32_t addr) {
    asm volatile("ldmatrix.sync.aligned.m8n8.x4.trans.shared.b16 {%0,%1,%2,%3}, [%4];"
                 : "=r"(r0), "=r"(r1), "=r"(r2), "=r"(r3) : "r"(addr));
}
__device__ __forceinline__ void mma16816(float* c, const uint32_t* a, const uint32_t* b) {
    asm volatile(
        "mma.sync.aligned.m16n8k16.row.col.f32.f16.f16.f32 "
        "{%0,%1,%2,%3},{%4,%5,%6,%7},{%8,%9},{%0,%1,%2,%3};"
        : "+f"(c[0]), "+f"(c[1]), "+f"(c[2]), "+f"(c[3])
        : "r"(a[0]), "r"(a[1]), "r"(a[2]), "r"(a[3]), "r"(b[0]), "r"(b[1]));
}
__device__ __forceinline__ void cpasync16(uint32_t smem, const void* g) {
    asm volatile("cp.async.cg.shared.global [%0], [%1], 16;" :: "r"(smem), "l"(g));
}
#define CP_COMMIT() asm volatile("cp.async.commit_group;" ::: "memory")
#define CP_WAIT0()  asm volatile("cp.async.wait_group 0;" ::: "memory")

__device__ __forceinline__ uint32_t hpack(float x, float y) {
    __half2 t = __floats2half2_rn(x, y);
    return *(uint32_t*)&t;
}
__device__ __forceinline__ uint32_t hpack_lo(float x, float y, uint32_t hi) {
    __half2 h = *(__half2*)&hi;
    return hpack(x - __half2float(h.x), y - __half2float(h.y));
}

// ---------------- 1. CPB MLP ----------------
__global__ void cpb_kernel(const float* __restrict__ tb, const float* __restrict__ w1,
                           const float* __restrict__ b1, const float* __restrict__ w2) {
    int r = blockIdx.x;
    float c0 = tb[r * 3 + 0], c1 = tb[r * 3 + 1], c2 = tb[r * 3 + 2];
    float acc[HH] = {0.f, 0.f, 0.f, 0.f, 0.f, 0.f};
    for (int j = threadIdx.x; j < 512; j += 128) {
        float hv = fmaf(c0, w1[j * 3 + 0], fmaf(c1, w1[j * 3 + 1], fmaf(c2, w1[j * 3 + 2], b1[j])));
        hv = fmaxf(hv, 0.f);
#pragma unroll
        for (int h = 0; h < HH; h++) acc[h] = fmaf(hv, w2[h * 512 + j], acc[h]);
    }
    __shared__ float red[HH][128];
#pragma unroll
    for (int h = 0; h < HH; h++) red[h][threadIdx.x] = acc[h];
    __syncthreads();
    for (int s = 64; s > 0; s >>= 1) {
        if (threadIdx.x < s) {
#pragma unroll
            for (int h = 0; h < HH; h++) red[h][threadIdx.x] += red[h][threadIdx.x + s];
        }
        __syncthreads();
    }
    if (threadIdx.x < HH) {
        float v = red[threadIdx.x][0];
        g_tbl[r * HH + threadIdx.x] = 16.f / (1.f + __expf(-v));
    }
}

// ---------------- 2. fused prep (expansions + fragment-layout bias/mask) ----------------
#define NB_XA   ((BW * NT * CC) / 256)        // 24576
#define NB_WQ   ((3 * CC * CC) / 256)         // 432
#define NB_WP   ((CC * CC) / 256)             // 144
#define NB_BF   ((HH * 8 * 4 * 8 * 8 * 32) / 256)     // 1536
#define NB_MF   ((NWIN * 8 * 4 * 8 * 8 * 32) / 256)   // 4096
__global__ void prep_kernel(const float* __restrict__ x, const float* __restrict__ qkv_w,
                            const float* __restrict__ proj_w, const int* __restrict__ rel_index,
                            const float* __restrict__ mask) {
    int bid = blockIdx.x;
    if (bid < NB_XA) {
        int i = bid * 256 + threadIdx.x;
        float a = x[i];
        __half hi = __float2half_rn(a);
        __half lo = __float2half_rn(a - __half2float(hi));
        int m = i / CC, k = i - m * CC;
        size_t o = (size_t)m * KE2 + k;
        g_xE[o] = hi; g_xE[o + CC] = lo;
    } else if (bid < NB_XA + NB_WQ) {
        int i = (bid - NB_XA) * 256 + threadIdx.x;
        __half hi = __float2half_rn(qkv_w[i]);
        int n = i / CC, k = i - n * CC;
        size_t o = (size_t)n * KE2 + k;
        g_wqkvE[o] = hi; g_wqkvE[o + CC] = hi;
    } else if (bid < NB_XA + NB_WQ + NB_WP) {
        int i = (bid - NB_XA - NB_WQ) * 256 + threadIdx.x;
        __half hi = __float2half_rn(proj_w[i]);
        int n = i / CC, k = i - n * CC;
        size_t o = (size_t)n * KE2 + k;
        g_wprojE[o] = hi; g_wprojE[o + CC] = hi;
    } else if (bid < NB_XA + NB_WQ + NB_WP + NB_BF) {
        int t = (bid - NB_XA - NB_WQ - NB_WP) * 256 + threadIdx.x;
        int lane = t & 31, j = (t >> 5) & 7, jt = (t >> 8) & 7;
        int wd = (t >> 11) & 3, ib = (t >> 13) & 7, h = t >> 16;
        int row = ib * 64 + wd * 16 + (lane >> 2);
        int col = jt * 64 + j * 8 + (lane & 3) * 2;
        int i0 = rel_index[row * NT + col];
        int i1 = rel_index[row * NT + col + 1];
        int i2 = rel_index[(row + 8) * NT + col];
        int i3 = rel_index[(row + 8) * NT + col + 1];
        float4 v = make_float4(g_tbl[i0 * HH + h], g_tbl[i1 * HH + h],
                               g_tbl[i2 * HH + h], g_tbl[i3 * HH + h]);
        *(float4*)(g_biasF + (size_t)t * 4) = v;
    } else {
        int t = (bid - NB_XA - NB_WQ - NB_WP - NB_BF) * 256 + threadIdx.x;
        int lane = t & 31, j = (t >> 5) & 7, jt = (t >> 8) & 7;
        int wd = (t >> 11) & 3, ib = (t >> 13) & 7, w = t >> 16;
        int row = ib * 64 + wd * 16 + (lane >> 2);
        int col = jt * 64 + j * 8 + (lane & 3) * 2;
        const float* mr0 = mask + ((size_t)w * NT + row) * NT + col;
        const float* mr1 = mask + ((size_t)w * NT + row + 8) * NT + col;
        float4 v = make_float4(mr0[0], mr0[1], mr1[0], mr1[1]);
        *(float4*)(g_maskF + (size_t)t * 4) = v;
    }
}

// ---------------- A-resident mma.sync GEMM ----------------
// CTA: 128 M-rows, full A tile (128 x 384 fp16 = 96KB) staged once in smem.
// N streamed as NP panels of 64 cols through a 2x8KB B double-buffer.
// MODE 0: NP=9 (N=576, qkv), epilogue bias+norm+scatter. MODE 1: NP=3 (proj).
#define SMA_BYTES 98304     // 6 chunk-panels x 16KB
#define SMB_BYTES 8192
template <int MODE>
__global__ void __launch_bounds__(256) mma_gemm(const float* __restrict__ bq,
                                                const float* __restrict__ bv,
                                                const float* __restrict__ lsc,
                                                float* __restrict__ Cout) {
    extern __shared__ __align__(128) unsigned char smem_all[];
    const int NP = (MODE == 0) ? 9 : 3;

    const int tid = threadIdx.x;
    const int wid = tid >> 5, lane = tid & 31;
    const int wm = wid >> 1, wn = wid & 1;
    const int m0 = blockIdx.y * 128;

    const __half* AE = (MODE == 0) ? g_xE : g_attE;
    const __half* BE = (MODE == 0) ? g_wqkvE : g_wprojE;

    const int li = lane & 7, lg = lane >> 3;
    const uint32_t sAu = s2u(smem_all), sBu = s2u(smem_all + SMA_BYTES);
    const int rowA0 = wm * 32 + li + (lg & 1) * 8;
    const int chA = lg >> 1;
    const int rowB0 = wn * 32 + li + (lg >> 1) * 8;
    const int chB = lg & 1;
    const int grow = tid >> 3, gseg = tid & 7;

    // ---- stage full A tile (24 x cp.async per thread), one commit ----
#pragma unroll
    for (int it = 0; it < 24; it++) {
        int idx = tid + it * 256;           // 0..6143
        int seg = idx & 7, row = (idx >> 3) & 127, c = idx >> 10;
        cpasync16(sAu + c * 16384 + SWZ(row * 128 + seg * 16),
                  AE + (size_t)(m0 + row) * KE2 + c * 64 + seg * 8);
    }
    CP_COMMIT();

    // ---- stage first B panel chunk ----
#define BSTAGE(np, c, buf) { \
        uint32_t bB = sBu + (buf) * SMB_BYTES; \
        _Pragma("unroll") \
        for (int it = 0; it < 2; it++) { \
            int row = grow + it * 32; \
            cpasync16(bB + SWZ(row * 128 + gseg * 16), \
                      BE + (size_t)((np) * 64 + row) * KE2 + (c) * 64 + gseg * 8); \
        } \
        CP_COMMIT(); }

    BSTAGE(0, 0, 0);

    const int qid = lane & 3;
    int buf = 0;
    for (int np = 0; np < NP; np++) {
        float acc[2][4][4];
#pragma unroll
        for (int t = 0; t < 2; t++)
#pragma unroll
            for (int nt = 0; nt < 4; nt++)
#pragma unroll
                for (int j = 0; j < 4; j++) acc[t][nt][j] = 0.f;

        for (int c = 0; c < 6; c++) {
            CP_WAIT0();
            __syncthreads();
            int u = np * 6 + c;
            if (u + 1 < NP * 6) {
                int nn = (u + 1) / 6, nc = (u + 1) % 6;
                BSTAGE(nn, nc, buf ^ 1);
            }

            uint32_t aB = sAu + c * 16384;
            uint32_t bB = sBu + buf * SMB_BYTES;
#pragma unroll
            for (int s = 0; s < 4; s++) {
                uint32_t a[2][4], b[2][4];
#pragma unroll
                for (int t = 0; t < 2; t++) {
                    int row = rowA0 + t * 16;
                    uint32_t addr = aB + row * 128 + (((2 * s + chA) ^ (row & 7)) << 4);
                    ldsm4(a[t][0], a[t][1], a[t][2], a[t][3], addr);
                }
#pragma unroll
                for (int p = 0; p < 2; p++) {
                    int row = rowB0 + p * 16;
                    uint32_t addr = bB + row * 128 + (((2 * s + chB) ^ (row & 7)) << 4);
                    ldsm4(b[p][0], b[p][1], b[p][2], b[p][3], addr);
                }
#pragma unroll
                for (int t = 0; t < 2; t++)
#pragma unroll
                    for (int nt = 0; nt < 4; nt++)
                        mma16816(acc[t][nt], a[t], &b[nt >> 1][(nt & 1) * 2]);
            }
            buf ^= 1;
        }

        // ---- epilogue for this panel ----
        const int nglob = np * 64 + wn * 32;
        if (MODE == 0) {
            const int s = nglob / 192;
            const int rem = nglob - s * 192;
            const int h = rem >> 5;
            float mulq = 0.f;
            if (s == 0) mulq = __expf(fminf(lsc[h], 4.605170186f));
#pragma unroll
            for (int t = 0; t < 2; t++) {
#pragma unroll
                for (int half = 0; half < 2; half++) {
                    int mrow = m0 + wm * 32 + t * 16 + half * 8 + (lane >> 2);
                    float f[8];
#pragma unroll
                    for (int nt = 0; nt < 4; nt++) {
                        int d0 = nt * 8 + qid * 2;
                        float b0 = (s == 0) ? bq[rem + d0] : ((s == 2) ? bv[rem + d0] : 0.f);
                        float b1 = (s == 0) ? bq[rem + d0 + 1] : ((s == 2) ? bv[rem + d0 + 1] : 0.f);
                        f[nt * 2 + 0] = acc[t][nt][half * 2 + 0] + b0;
                        f[nt * 2 + 1] = acc[t][nt][half * 2 + 1] + b1;
                    }
                    float mul = 1.f;
                    if (s < 2) {
                        float ss = 0.f;
#pragma unroll
                        for (int j = 0; j < 8; j++) ss = fmaf(f[j], f[j], ss);
                        ss += __shfl_xor_sync(0xffffffffu, ss, 1);
                        ss += __shfl_xor_sync(0xffffffffu, ss, 2);
                        mul = 1.f / fmaxf(sqrtf(ss), 1e-12f);
                        if (s == 0) mul *= mulq;
                    }
                    const int bb = mrow >> 9, nr = mrow & 511;
                    if (s == 0) {
                        float* op = g_q + ((((size_t)bb * HH + h) << 9) + nr) * HD;
#pragma unroll
                        for (int nt = 0; nt < 4; nt++) {
                            int d0 = nt * 8 + qid * 2;
                            *(float2*)(op + d0) = make_float2(f[nt * 2] * mul, f[nt * 2 + 1] * mul);
                        }
                    } else {
                        __half* op = (s == 1 ? g_kE : g_vE) +
                                     ((((size_t)bb * HH + h) << 9) + nr) * 32;
#pragma unroll
                        for (int nt = 0; nt < 4; nt++) {
                            int d0 = nt * 8 + qid * 2;
                            *(uint32_t*)(op + d0) = hpack(f[nt * 2] * mul, f[nt * 2 + 1] * mul);
                        }
                    }
                }
            }
        } else {
#pragma unroll
            for (int t = 0; t < 2; t++) {
#pragma unroll
                for (int half = 0; half < 2; half++) {
                    int mrow = m0 + wm * 32 + t * 16 + half * 8 + (lane >> 2);
                    float* op = Cout + (size_t)mrow * CC + nglob;
#pragma unroll
                    for (int nt = 0; nt < 4; nt++) {
                        int d0 = nt * 8 + qid * 2;
                        float pb0 = bq[nglob + d0], pb1 = bq[nglob + d0 + 1];
                        *(float2*)(op + d0) = make_float2(acc[t][nt][half * 2 + 0] + pb0,
                                                          acc[t][nt][half * 2 + 1] + pb1);
                    }
                }
            }
        }
    }
#undef BSTAGE
}

// ---------------- tensor-core flash attention (unchanged from R13) ----------------
#define PANEL 5120
__global__ void __launch_bounds__(128, 5) attn_mma() {
    const int b = blockIdx.z, h = blockIdx.y;
    const int i0 = blockIdx.x * 64;
    const int w = b & (NWIN - 1);
    const int tid = threadIdx.x, wid = tid >> 5, lane = tid & 31;
    const int qd = lane & 3, r = lane >> 2;

    __shared__ __align__(16) unsigned char sK[2 * PANEL];
    __shared__ __align__(16) unsigned char sV[2 * PANEL];
    const uint32_t sKu = s2u(sK), sVu = s2u(sV);

    const __half* kgE = g_kE + (((size_t)(b * HH + h)) << 9) * 32;
    const __half* vgE = g_vE + (((size_t)(b * HH + h)) << 9) * 32;
    const int crow = tid >> 1, chalf = (tid & 1) * 32;

#define CPKV(jt, buf) { \
        const __half* kr = kgE + (size_t)((jt) * 64 + crow) * 32; \
        const __half* vr = vgE + (size_t)((jt) * 64 + crow) * 32; \
        uint32_t kd = sKu + (buf) * PANEL + crow * 80 + chalf; \
        uint32_t vd = sVu + (buf) * PANEL + crow * 80 + chalf; \
        cpasync16(kd,      (const char*)kr + chalf); \
        cpasync16(kd + 16, (const char*)kr + chalf + 16); \
        cpasync16(vd,      (const char*)vr + chalf); \
        cpasync16(vd + 16, (const char*)vr + chalf + 16); \
        CP_COMMIT(); }

    CPKV(0, 0);

    const int rowg = i0 + wid * 16 + r;
    const float* qrowA = g_q + (((size_t)(b * HH + h) << 9) + rowg) * HD;
    const float* qrowB = qrowA + 8 * HD;
    uint32_t Ahi[2][4], Alo[2][4];
#pragma unroll
    for (int c = 0; c < 2; c++) {
        float2 fa0 = *(const float2*)(qrowA + 2 * qd + 16 * c);
        float2 fb0 = *(const float2*)(qrowB + 2 * qd + 16 * c);
        float2 fa1 = *(const float2*)(qrowA + 2 * qd + 16 * c + 8);
        float2 fb1 = *(const float2*)(qrowB + 2 * qd + 16 * c + 8);
        Ahi[c][0] = hpack(fa0.x, fa0.y); Alo[c][0] = hpack_lo(fa0.x, fa0.y, Ahi[c][0]);
        Ahi[c][1] = hpack(fb0.x, fb0.y); Alo[c][1] = hpack_lo(fb0.x, fb0.y, Ahi[c][1]);
        Ahi[c][2] = hpack(fa1.x, fa1.y); Alo[c][2] = hpack_lo(fa1.x, fa1.y, Ahi[c][2]);
        Ahi[c][3] = hpack(fb1.x, fb1.y); Alo[c][3] = hpack_lo(fb1.x, fb1.y, Ahi[c][3]);
    }

    const int li = lane & 7, lg = lane >> 3;
    const uint32_t kbase = sKu + (((lg >> 1) * 8 + li) * 80) + (lg & 1) * 16;
    const uint32_t vbase = sVu + (((lg & 1) * 8 + li) * 80) + (lg >> 1) * 16;

    const float* pbF = g_biasF + ((size_t)((h * 8 + blockIdx.x) * 4 + wid) * 8) * 1024 + lane * 4;
    const float* pmF = g_maskF + ((size_t)((w * 8 + blockIdx.x) * 4 + wid) * 8) * 1024 + lane * 4;

    float O[4][4];
#pragma unroll
    for (int j = 0; j < 4; j++)
#pragma unroll
        for (int u = 0; u < 4; u++) O[j][u] = 0.f;
    float m0v = -1e30f, m1v = -1e30f, lsum0 = 0.f, lsum1 = 0.f;

    for (int jt = 0; jt < 8; jt++) {
        const int buf = jt & 1;
        CP_WAIT0();
        __syncthreads();
        if (jt < 7) CPKV(jt + 1, buf ^ 1);

        float s[8][4];
        const float* pbT = pbF + jt * 1024;
        const float* pmT = pmF + jt * 1024;
#pragma unroll
        for (int j = 0; j < 8; j++) {
            float4 bb = *(const float4*)(pbT + j * 128);
            float4 mm = *(const float4*)(pmT + j * 128);
            s[j][0] = bb.x + mm.x; s[j][1] = bb.y + mm.y;
            s[j][2] = bb.z + mm.z; s[j][3] = bb.w + mm.w;
        }

#pragma unroll
        for (int jph = 0; jph < 2; jph++) {
            uint32_t H0[8], H1[8];
            {
                uint32_t base0 = kbase + buf * PANEL + (2 * jph)     * 16 * 80;
                uint32_t base1 = kbase + buf * PANEL + (2 * jph + 1) * 16 * 80;
                ldsm4(H0[0], H0[1], H0[2], H0[3], base0 + 0);
                ldsm4(H0[4], H0[5], H0[6], H0[7], base0 + 32);
                ldsm4(H1[0], H1[1], H1[2], H1[3], base1 + 0);
                ldsm4(H1[4], H1[5], H1[6], H1[7], base1 + 32);
            }
            float* s0 = s[4 * jph + 0]; float* s1 = s[4 * jph + 1];
            float* s2 = s[4 * jph + 2]; float* s3 = s[4 * jph + 3];
            mma16816(s0, Ahi[0], H0 + 0); mma16816(s1, Ahi[0], H0 + 2);
            mma16816(s2, Ahi[0], H1 + 0); mma16816(s3, Ahi[0], H1 + 2);
            mma16816(s0, Ahi[1], H0 + 4); mma16816(s1, Ahi[1], H0 + 6);
            mma16816(s2, Ahi[1], H1 + 4); mma16816(s3, Ahi[1], H1 + 6);
            mma16816(s0, Alo[0], H0 + 0); mma16816(s1, Alo[0], H0 + 2);
            mma16816(s2, Alo[0], H1 + 0); mma16816(s3, Alo[0], H1 + 2);
            mma16816(s0, Alo[1], H0 + 4); mma16816(s1, Alo[1], H0 + 6);
            mma16816(s2, Alo[1], H1 + 4); mma16816(s3, Alo[1], H1 + 6);
        }

        float tm0 = -1e30f, tm1 = -1e30f;
#pragma unroll
        for (int j = 0; j < 8; j++) {
            tm0 = fmaxf(tm0, fmaxf(s[j][0], s[j][1]));
            tm1 = fmaxf(tm1, fmaxf(s[j][2], s[j][3]));
        }
        tm0 = fmaxf(tm0, __shfl_xor_sync(0xffffffffu, tm0, 1));
        tm0 = fmaxf(tm0, __shfl_xor_sync(0xffffffffu, tm0, 2));
        tm1 = fmaxf(tm1, __shfl_xor_sync(0xffffffffu, tm1, 1));
        tm1 = fmaxf(tm1, __shfl_xor_sync(0xffffffffu, tm1, 2));
        float mn0 = fmaxf(m0v, tm0), mn1 = fmaxf(m1v, tm1);
        float c0 = __expf(m0v - mn0), c1 = __expf(m1v - mn1);
        m0v = mn0; m1v = mn1;
        lsum0 *= c0; lsum1 *= c1;
#pragma unroll
        for (int j = 0; j < 4; j++) {
            O[j][0] *= c0; O[j][1] *= c0; O[j][2] *= c1; O[j][3] *= c1;
        }
#pragma unroll
        for (int j = 0; j < 8; j++) {
            s[j][0] = __expf(s[j][0] - mn0); s[j][1] = __expf(s[j][1] - mn0);
            s[j][2] = __expf(s[j][2] - mn1); s[j][3] = __expf(s[j][3] - mn1);
            lsum0 += s[j][0] + s[j][1];
            lsum1 += s[j][2] + s[j][3];
        }

#pragma unroll
        for (int c = 0; c < 4; c++) {
            uint32_t Ph[4], Pl[4];
            Ph[0] = hpack(s[2 * c][0], s[2 * c][1]);
            Pl[0] = hpack_lo(s[2 * c][0], s[2 * c][1], Ph[0]);
            Ph[1] = hpack(s[2 * c][2], s[2 * c][3]);
            Pl[1] = hpack_lo(s[2 * c][2], s[2 * c][3], Ph[1]);
            Ph[2] = hpack(s[2 * c + 1][0], s[2 * c + 1][1]);
            Pl[2] = hpack_lo(s[2 * c + 1][0], s[2 * c + 1][1], Ph[2]);
            Ph[3] = hpack(s[2 * c + 1][2], s[2 * c + 1][3]);
            Pl[3] = hpack_lo(s[2 * c + 1][2], s[2 * c + 1][3], Ph[3]);
            uint32_t v0[4], v1[4];
            uint32_t base = vbase + buf * PANEL + c * 16 * 80;
            ldsm4t(v0[0], v0[1], v0[2], v0[3], base);
            ldsm4t(v1[0], v1[1], v1[2], v1[3], base + 32);
            mma16816(O[0], Ph, v0 + 0); mma16816(O[1], Ph, v0 + 2);
            mma16816(O[2], Ph, v1 + 0); mma16816(O[3], Ph, v1 + 2);
            mma16816(O[0], Pl, v0 + 0); mma16816(O[1], Pl, v0 + 2);
            mma16816(O[2], Pl, v1 + 0); mma16816(O[3], Pl, v1 + 2);
        }
    }
#undef CPKV

    lsum0 += __shfl_xor_sync(0xffffffffu, lsum0, 1);
    lsum0 += __shfl_xor_sync(0xffffffffu, lsum0, 2);
    lsum1 += __shfl_xor_sync(0xffffffffu, lsum1, 1);
    lsum1 += __shfl_xor_sync(0xffffffffu, lsum1, 2);
    float inv0 = 1.f / lsum0, inv1 = 1.f / lsum1;

    __half* baseA = g_attE + (size_t)(b * NT + rowg) * KE2 + h * HD + 2 * qd;
    __half* baseB = baseA + (size_t)8 * KE2;
#pragma unroll
    for (int j = 0; j < 4; j++) {
        int col = j * 8;
        uint32_t hiA = hpack(O[j][0] * inv0, O[j][1] * inv0);
        uint32_t loA = hpack_lo(O[j][0] * inv0, O[j][1] * inv0, hiA);
        *(uint32_t*)(baseA + col)      = hiA;
        *(uint32_t*)(baseA + col + CC) = loA;
        uint32_t hiB = hpack(O[j][2] * inv1, O[j][3] * inv1);
        uint32_t loB = hpack_lo(O[j][2] * inv1, O[j][3] * inv1, hiB);
        *(uint32_t*)(baseB + col)      = hiB;
        *(uint32_t*)(baseB + col + CC) = loB;
    }
}

// ---------------- launch ----------------
extern "C" void kernel_launch(void* const* d_in, const int* in_sizes, int n_in,
                              void* d_out, int out_size) {
    const float* x           = (const float*)d_in[0];
    const float* mask        = (const float*)d_in[1];
    const float* qkv_w       = (const float*)d_in[2];
    const float* q_bias      = (const float*)d_in[3];
    const float* v_bias      = (const float*)d_in[4];
    const float* logit_scale = (const float*)d_in[5];
    const float* cpb_w1      = (const float*)d_in[6];
    const float* cpb_b1      = (const float*)d_in[7];
    const float* cpb_w2      = (const float*)d_in[8];
    const float* proj_w      = (const float*)d_in[9];
    const float* proj_b      = (const float*)d_in[10];
    const float* rel_table   = (const float*)d_in[11];
    const int*   rel_index   = (const int*)d_in[12];
    float* out = (float*)d_out;

    const int gemm_smem = SMA_BYTES + 2 * SMB_BYTES;   // 114688
    cudaFuncSetAttribute(mma_gemm<0>, cudaFuncAttributeMaxDynamicSharedMemorySize, gemm_smem);
    cudaFuncSetAttribute(mma_gemm<1>, cudaFuncAttributeMaxDynamicSharedMemorySize, gemm_smem);

    cpb_kernel<<<TBL, 128>>>(rel_table, cpb_w1, cpb_b1, cpb_w2);
    prep_kernel<<<NB_XA + NB_WQ + NB_WP + NB_BF + NB_MF, 256>>>(x, qkv_w, proj_w, rel_index, mask);
    mma_gemm<0><<<dim3(1, 256), 256, gemm_smem>>>(q_bias, v_bias, logit_scale, nullptr);
    attn_mma<<<dim3(8, HH, BW), 128>>>();
    mma_gemm<1><<<dim3(1, 256), 256, gemm_smem>>>(proj_b, nullptr, nullptr, out);
}

// round 15
// speedup vs baseline: 1.0839x; 1.0839x over previous
#include <cuda_runtime.h>
#include <cuda_fp16.h>
#include <cstdint>

// ---------------- problem constants ----------------
#define BW   64
#define NT   512
#define CC   192
#define HH   6
#define HD   32
#define NWIN 16
#define TBL  3375
#define KE2  384           // expanded K = 2*192 (fp16 hi|lo)

// ---------------- device scratch ----------------
__device__ float g_tbl[TBL * HH];
// bias/mask in mma-fragment layout: [h|w][iblk(8)][warp(4)][jt(8)][j(8)][lane(32)][4]
__device__ float g_biasF[HH * 8 * 4 * 8 * 8 * 32 * 4];      // 6.3 MB
__device__ float g_maskF[NWIN * 8 * 4 * 8 * 8 * 32 * 4];    // 16.8 MB
__device__ float g_q[BW * HH * NT * HD];
// k/v stored as fp16 hi only: 32 halfs (64B) per key
__device__ __half g_kE[(size_t)BW * HH * NT * 32];
__device__ __half g_vE[(size_t)BW * HH * NT * 32];
__device__ __half g_xE[(size_t)BW * NT * KE2];     // x expanded [hi|lo]
__device__ __half g_attE[(size_t)BW * NT * KE2];   // attn out expanded [hi|lo]
__device__ __half g_wqkvE[3 * CC * KE2];           // qkv_w expanded [hi|hi]
__device__ __half g_wprojE[CC * KE2];              // proj_w expanded [hi|hi]

#define SWZ(o) ((o) ^ (((o) >> 3) & 0x70))

__device__ __forceinline__ uint32_t s2u(const void* p) {
    return (uint32_t)__cvta_generic_to_shared(p);
}
__device__ __forceinline__ void ldsm4(uint32_t& r0, uint32_t& r1, uint32_t& r2, uint32_t& r3,
                                      uint32_t addr) {
    asm volatile("ldmatrix.sync.aligned.m8n8.x4.shared.b16 {%0,%1,%2,%3}, [%4];"
                 : "=r"(r0), "=r"(r1), "=r"(r2), "=r"(r3) : "r"(addr));
}
__device__ __forceinline__ void ldsm4t(uint32_t& r0, uint32_t& r1, uint32_t& r2, uint32_t& r3,
                                       uint32_t addr) {
    asm volatile("ldmatrix.sync.aligned.m8n8.x4.trans.shared.b16 {%0,%1,%2,%3}, [%4];"
                 : "=r"(r0), "=r"(r1), "=r"(r2), "=r"(r3) : "r"(addr));
}
__device__ __forceinline__ void mma16816(float* c, const uint32_t* a, const uint32_t* b) {
    asm volatile(
        "mma.sync.aligned.m16n8k16.row.col.f32.f16.f16.f32 "
        "{%0,%1,%2,%3},{%4,%5,%6,%7},{%8,%9},{%0,%1,%2,%3};"
        : "+f"(c[0]), "+f"(c[1]), "+f"(c[2]), "+f"(c[3])
        : "r"(a[0]), "r"(a[1]), "r"(a[2]), "r"(a[3]), "r"(b[0]), "r"(b[1]));
}
__device__ __forceinline__ void cpasync16(uint32_t smem, const void* g) {
    asm volatile("cp.async.cg.shared.global [%0], [%1], 16;" :: "r"(smem), "l"(g));
}
#define CP_COMMIT() asm volatile("cp.async.commit_group;" ::: "memory")
#define CP_WAIT0()  asm volatile("cp.async.wait_group 0;" ::: "memory")

__device__ __forceinline__ uint32_t hpack(float x, float y) {
    __half2 t = __floats2half2_rn(x, y);
    return *(uint32_t*)&t;
}
__device__ __forceinline__ uint32_t hpack_lo(float x, float y, uint32_t hi) {
    __half2 h = *(__half2*)&hi;
    return hpack(x - __half2float(h.x), y - __half2float(h.y));
}

// ---------------- 1. CPB MLP ----------------
__global__ void cpb_kernel(const float* __restrict__ tb, const float* __restrict__ w1,
                           const float* __restrict__ b1, const float* __restrict__ w2) {
    int r = blockIdx.x;
    float c0 = tb[r * 3 + 0], c1 = tb[r * 3 + 1], c2 = tb[r * 3 + 2];
    float acc[HH] = {0.f, 0.f, 0.f, 0.f, 0.f, 0.f};
    for (int j = threadIdx.x; j < 512; j += 128) {
        float hv = fmaf(c0, w1[j * 3 + 0], fmaf(c1, w1[j * 3 + 1], fmaf(c2, w1[j * 3 + 2], b1[j])));
        hv = fmaxf(hv, 0.f);
#pragma unroll
        for (int h = 0; h < HH; h++) acc[h] = fmaf(hv, w2[h * 512 + j], acc[h]);
    }
    __shared__ float red[HH][128];
#pragma unroll
    for (int h = 0; h < HH; h++) red[h][threadIdx.x] = acc[h];
    __syncthreads();
    for (int s = 64; s > 0; s >>= 1) {
        if (threadIdx.x < s) {
#pragma unroll
            for (int h = 0; h < HH; h++) red[h][threadIdx.x] += red[h][threadIdx.x + s];
        }
        __syncthreads();
    }
    if (threadIdx.x < HH) {
        float v = red[threadIdx.x][0];
        g_tbl[r * HH + threadIdx.x] = 16.f / (1.f + __expf(-v));
    }
}

// ---------------- 2. fused prep (expansions + fragment-layout bias/mask) ----------------
#define NB_XA   ((BW * NT * CC) / 256)        // 24576
#define NB_WQ   ((3 * CC * CC) / 256)         // 432
#define NB_WP   ((CC * CC) / 256)             // 144
#define NB_BF   ((HH * 8 * 4 * 8 * 8 * 32) / 256)     // 1536
#define NB_MF   ((NWIN * 8 * 4 * 8 * 8 * 32) / 256)   // 4096
__global__ void prep_kernel(const float* __restrict__ x, const float* __restrict__ qkv_w,
                            const float* __restrict__ proj_w, const int* __restrict__ rel_index,
                            const float* __restrict__ mask) {
    int bid = blockIdx.x;
    if (bid < NB_XA) {
        int i = bid * 256 + threadIdx.x;
        float a = x[i];
        __half hi = __float2half_rn(a);
        __half lo = __float2half_rn(a - __half2float(hi));
        int m = i / CC, k = i - m * CC;
        size_t o = (size_t)m * KE2 + k;
        g_xE[o] = hi; g_xE[o + CC] = lo;
    } else if (bid < NB_XA + NB_WQ) {
        int i = (bid - NB_XA) * 256 + threadIdx.x;
        __half hi = __float2half_rn(qkv_w[i]);
        int n = i / CC, k = i - n * CC;
        size_t o = (size_t)n * KE2 + k;
        g_wqkvE[o] = hi; g_wqkvE[o + CC] = hi;
    } else if (bid < NB_XA + NB_WQ + NB_WP) {
        int i = (bid - NB_XA - NB_WQ) * 256 + threadIdx.x;
        __half hi = __float2half_rn(proj_w[i]);
        int n = i / CC, k = i - n * CC;
        size_t o = (size_t)n * KE2 + k;
        g_wprojE[o] = hi; g_wprojE[o + CC] = hi;
    } else if (bid < NB_XA + NB_WQ + NB_WP + NB_BF) {
        int t = (bid - NB_XA - NB_WQ - NB_WP) * 256 + threadIdx.x;
        int lane = t & 31, j = (t >> 5) & 7, jt = (t >> 8) & 7;
        int wd = (t >> 11) & 3, ib = (t >> 13) & 7, h = t >> 16;
        int row = ib * 64 + wd * 16 + (lane >> 2);
        int col = jt * 64 + j * 8 + (lane & 3) * 2;
        int i0 = rel_index[row * NT + col];
        int i1 = rel_index[row * NT + col + 1];
        int i2 = rel_index[(row + 8) * NT + col];
        int i3 = rel_index[(row + 8) * NT + col + 1];
        float4 v = make_float4(g_tbl[i0 * HH + h], g_tbl[i1 * HH + h],
                               g_tbl[i2 * HH + h], g_tbl[i3 * HH + h]);
        *(float4*)(g_biasF + (size_t)t * 4) = v;
    } else {
        int t = (bid - NB_XA - NB_WQ - NB_WP - NB_BF) * 256 + threadIdx.x;
        int lane = t & 31, j = (t >> 5) & 7, jt = (t >> 8) & 7;
        int wd = (t >> 11) & 3, ib = (t >> 13) & 7, w = t >> 16;
        int row = ib * 64 + wd * 16 + (lane >> 2);
        int col = jt * 64 + j * 8 + (lane & 3) * 2;
        const float* mr0 = mask + ((size_t)w * NT + row) * NT + col;
        const float* mr1 = mask + ((size_t)w * NT + row + 8) * NT + col;
        float4 v = make_float4(mr0[0], mr0[1], mr1[0], mr1[1]);
        *(float4*)(g_maskF + (size_t)t * 4) = v;
    }
}

// ---------------- mma.sync GEMM: block 128(M) x 64(N), K'=384, cp.async 2-stage (R13) ----------------
template <int MODE>
__global__ void __launch_bounds__(256) mma_gemm(const float* __restrict__ bq,
                                                const float* __restrict__ bv,
                                                const float* __restrict__ lsc,
                                                float* __restrict__ Cout) {
    __shared__ __align__(128) unsigned char smem_all[49152];

    const int tid = threadIdx.x;
    const int wid = tid >> 5, lane = tid & 31;
    const int wm = wid >> 1, wn = wid & 1;
    const int m0 = blockIdx.y * 128;
    const int n0 = blockIdx.x * 64;

    const __half* AE = (MODE == 0) ? g_xE : g_attE;
    const __half* BE = (MODE == 0) ? g_wqkvE : g_wprojE;

    float acc[2][4][4];
#pragma unroll
    for (int t = 0; t < 2; t++)
#pragma unroll
        for (int nt = 0; nt < 4; nt++)
#pragma unroll
            for (int j = 0; j < 4; j++) acc[t][nt][j] = 0.f;

    const int li = lane & 7, lg = lane >> 3;
    const uint32_t sAu = s2u(smem_all), sBu = s2u(smem_all + 32768);
    const int rowA0 = wm * 32 + li + (lg & 1) * 8;
    const int chA = lg >> 1;
    const int rowB0 = wn * 32 + li + (lg >> 1) * 8;
    const int chB = lg & 1;

    const int grow = tid >> 3, gseg = tid & 7;

#define GSTAGE(c, buf) { \
        uint32_t aB = sAu + (buf) * 16384; \
        uint32_t bB = sBu + (buf) * 8192;  \
        _Pragma("unroll") \
        for (int it = 0; it < 4; it++) { \
            int row = grow + it * 32; \
            cpasync16(aB + SWZ(row * 128 + gseg * 16), \
                      AE + (size_t)(m0 + row) * KE2 + (c) * 64 + gseg * 8); \
        } \
        _Pragma("unroll") \
        for (int it = 0; it < 2; it++) { \
            int row = grow + it * 32; \
            cpasync16(bB + SWZ(row * 128 + gseg * 16), \
                      BE + (size_t)(n0 + row) * KE2 + (c) * 64 + gseg * 8); \
        } \
        CP_COMMIT(); }

    GSTAGE(0, 0);

    for (int c = 0; c < 6; c++) {
        CP_WAIT0();
        __syncthreads();
        if (c < 5) GSTAGE(c + 1, (c + 1) & 1);

        uint32_t aB = sAu + (c & 1) * 16384;
        uint32_t bB = sBu + (c & 1) * 8192;
#pragma unroll
        for (int s = 0; s < 4; s++) {
            uint32_t a[2][4], b[2][4];
#pragma unroll
            for (int t = 0; t < 2; t++) {
                int row = rowA0 + t * 16;
                uint32_t addr = aB + row * 128 + (((2 * s + chA) ^ (row & 7)) << 4);
                ldsm4(a[t][0], a[t][1], a[t][2], a[t][3], addr);
            }
#pragma unroll
            for (int p = 0; p < 2; p++) {
                int row = rowB0 + p * 16;
                uint32_t addr = bB + row * 128 + (((2 * s + chB) ^ (row & 7)) << 4);
                ldsm4(b[p][0], b[p][1], b[p][2], b[p][3], addr);
            }
#pragma unroll
            for (int t = 0; t < 2; t++)
#pragma unroll
                for (int nt = 0; nt < 4; nt++)
                    mma16816(acc[t][nt], a[t], &b[nt >> 1][(nt & 1) * 2]);
        }
    }
#undef GSTAGE

    const int nglob = n0 + wn * 32;
    const int qid = lane & 3;
    if (MODE == 0) {
        const int s = nglob / 192;
        const int rem = nglob - s * 192;
        const int h = rem >> 5;
        float mulq = 0.f;
        if (s == 0) mulq = __expf(fminf(lsc[h], 4.605170186f));
#pragma unroll
        for (int t = 0; t < 2; t++) {
#pragma unroll
            for (int half = 0; half < 2; half++) {
                int mrow = m0 + wm * 32 + t * 16 + half * 8 + (lane >> 2);
                float f[8];
#pragma unroll
                for (int nt = 0; nt < 4; nt++) {
                    int d0 = nt * 8 + qid * 2;
                    float b0 = (s == 0) ? bq[rem + d0] : ((s == 2) ? bv[rem + d0] : 0.f);
                    float b1 = (s == 0) ? bq[rem + d0 + 1] : ((s == 2) ? bv[rem + d0 + 1] : 0.f);
                    f[nt * 2 + 0] = acc[t][nt][half * 2 + 0] + b0;
                    f[nt * 2 + 1] = acc[t][nt][half * 2 + 1] + b1;
                }
                float mul = 1.f;
                if (s < 2) {
                    float ss = 0.f;
#pragma unroll
                    for (int j = 0; j < 8; j++) ss = fmaf(f[j], f[j], ss);
                    ss += __shfl_xor_sync(0xffffffffu, ss, 1);
                    ss += __shfl_xor_sync(0xffffffffu, ss, 2);
                    mul = 1.f / fmaxf(sqrtf(ss), 1e-12f);
                    if (s == 0) mul *= mulq;
                }
                const int bb = mrow >> 9, nr = mrow & 511;
                if (s == 0) {
                    float* op = g_q + ((((size_t)bb * HH + h) << 9) + nr) * HD;
#pragma unroll
                    for (int nt = 0; nt < 4; nt++) {
                        int d0 = nt * 8 + qid * 2;
                        *(float2*)(op + d0) = make_float2(f[nt * 2] * mul, f[nt * 2 + 1] * mul);
                    }
                } else {
                    __half* op = (s == 1 ? g_kE : g_vE) +
                                 ((((size_t)bb * HH + h) << 9) + nr) * 32;
#pragma unroll
                    for (int nt = 0; nt < 4; nt++) {
                        int d0 = nt * 8 + qid * 2;
                        *(uint32_t*)(op + d0) = hpack(f[nt * 2] * mul, f[nt * 2 + 1] * mul);
                    }
                }
            }
        }
    } else {
#pragma unroll
        for (int t = 0; t < 2; t++) {
#pragma unroll
            for (int half = 0; half < 2; half++) {
                int mrow = m0 + wm * 32 + t * 16 + half * 8 + (lane >> 2);
                float* op = Cout + (size_t)mrow * CC + nglob;
#pragma unroll
                for (int nt = 0; nt < 4; nt++) {
                    int d0 = nt * 8 + qid * 2;
                    float pb0 = bq[nglob + d0], pb1 = bq[nglob + d0 + 1];
                    *(float2*)(op + d0) = make_float2(acc[t][nt][half * 2 + 0] + pb0,
                                                      acc[t][nt][half * 2 + 1] + pb1);
                }
            }
        }
    }
}

// ---------------- tensor-core flash attention ----------------
// 128-thread CTA (4 warps x 16 q-rows = 64 rows); 5 CTAs/SM.
// K/V smem panel: 64 keys x 64B (fp16 hi only), row stride 80B.
// Bias/mask from fragment-layout tables (coalesced LDG.128).
// PV uses P-hi only (fp16 2^-12 rounding; lo-term dropped).
#define PANEL 5120
__global__ void __launch_bounds__(128, 5) attn_mma() {
    const int b = blockIdx.z, h = blockIdx.y;
    const int i0 = blockIdx.x * 64;
    const int w = b & (NWIN - 1);
    const int tid = threadIdx.x, wid = tid >> 5, lane = tid & 31;
    const int qd = lane & 3, r = lane >> 2;

    __shared__ __align__(16) unsigned char sK[2 * PANEL];
    __shared__ __align__(16) unsigned char sV[2 * PANEL];
    const uint32_t sKu = s2u(sK), sVu = s2u(sV);

    const __half* kgE = g_kE + (((size_t)(b * HH + h)) << 9) * 32;
    const __half* vgE = g_vE + (((size_t)(b * HH + h)) << 9) * 32;
    const int crow = tid >> 1, chalf = (tid & 1) * 32;

#define CPKV(jt, buf) { \
        const __half* kr = kgE + (size_t)((jt) * 64 + crow) * 32; \
        const __half* vr = vgE + (size_t)((jt) * 64 + crow) * 32; \
        uint32_t kd = sKu + (buf) * PANEL + crow * 80 + chalf; \
        uint32_t vd = sVu + (buf) * PANEL + crow * 80 + chalf; \
        cpasync16(kd,      (const char*)kr + chalf); \
        cpasync16(kd + 16, (const char*)kr + chalf + 16); \
        cpasync16(vd,      (const char*)vr + chalf); \
        cpasync16(vd + 16, (const char*)vr + chalf + 16); \
        CP_COMMIT(); }

    CPKV(0, 0);

    // ---- Q fragments (hi/lo fp16) from fp32 g_q ----
    const int rowg = i0 + wid * 16 + r;
    const float* qrowA = g_q + (((size_t)(b * HH + h) << 9) + rowg) * HD;
    const float* qrowB = qrowA + 8 * HD;
    uint32_t Ahi[2][4], Alo[2][4];
#pragma unroll
    for (int c = 0; c < 2; c++) {
        float2 fa0 = *(const float2*)(qrowA + 2 * qd + 16 * c);
        float2 fb0 = *(const float2*)(qrowB + 2 * qd + 16 * c);
        float2 fa1 = *(const float2*)(qrowA + 2 * qd + 16 * c + 8);
        float2 fb1 = *(const float2*)(qrowB + 2 * qd + 16 * c + 8);
        Ahi[c][0] = hpack(fa0.x, fa0.y); Alo[c][0] = hpack_lo(fa0.x, fa0.y, Ahi[c][0]);
        Ahi[c][1] = hpack(fb0.x, fb0.y); Alo[c][1] = hpack_lo(fb0.x, fb0.y, Ahi[c][1]);
        Ahi[c][2] = hpack(fa1.x, fa1.y); Alo[c][2] = hpack_lo(fa1.x, fa1.y, Ahi[c][2]);
        Ahi[c][3] = hpack(fb1.x, fb1.y); Alo[c][3] = hpack_lo(fb1.x, fb1.y, Ahi[c][3]);
    }

    const int li = lane & 7, lg = lane >> 3;
    const uint32_t kbase = sKu + (((lg >> 1) * 8 + li) * 80) + (lg & 1) * 16;
    const uint32_t vbase = sVu + (((lg & 1) * 8 + li) * 80) + (lg >> 1) * 16;

    const float* pbF = g_biasF + ((size_t)((h * 8 + blockIdx.x) * 4 + wid) * 8) * 1024 + lane * 4;
    const float* pmF = g_maskF + ((size_t)((w * 8 + blockIdx.x) * 4 + wid) * 8) * 1024 + lane * 4;

    float O[4][4];
#pragma unroll
    for (int j = 0; j < 4; j++)
#pragma unroll
        for (int u = 0; u < 4; u++) O[j][u] = 0.f;
    float m0v = -1e30f, m1v = -1e30f, lsum0 = 0.f, lsum1 = 0.f;

    for (int jt = 0; jt < 8; jt++) {
        const int buf = jt & 1;
        CP_WAIT0();
        __syncthreads();
        if (jt < 7) CPKV(jt + 1, buf ^ 1);

        // ---- init S with bias + mask (coalesced fragment loads) ----
        float s[8][4];
        const float* pbT = pbF + jt * 1024;
        const float* pmT = pmF + jt * 1024;
#pragma unroll
        for (int j = 0; j < 8; j++) {
            float4 bb = *(const float4*)(pbT + j * 128);
            float4 mm = *(const float4*)(pmT + j * 128);
            s[j][0] = bb.x + mm.x; s[j][1] = bb.y + mm.y;
            s[j][2] = bb.z + mm.z; s[j][3] = bb.w + mm.w;
        }

        // ---- S += (qhi+qlo) . khi^T : 2 jp-blocks at a time, 4-way interleaved ----
#pragma unroll
        for (int jph = 0; jph < 2; jph++) {
            uint32_t H0[8], H1[8];
            {
                uint32_t base0 = kbase + buf * PANEL + (2 * jph)     * 16 * 80;
                uint32_t base1 = kbase + buf * PANEL + (2 * jph + 1) * 16 * 80;
                ldsm4(H0[0], H0[1], H0[2], H0[3], base0 + 0);
                ldsm4(H0[4], H0[5], H0[6], H0[7], base0 + 32);
                ldsm4(H1[0], H1[1], H1[2], H1[3], base1 + 0);
                ldsm4(H1[4], H1[5], H1[6], H1[7], base1 + 32);
            }
            float* s0 = s[4 * jph + 0]; float* s1 = s[4 * jph + 1];
            float* s2 = s[4 * jph + 2]; float* s3 = s[4 * jph + 3];
            mma16816(s0, Ahi[0], H0 + 0); mma16816(s1, Ahi[0], H0 + 2);
            mma16816(s2, Ahi[0], H1 + 0); mma16816(s3, Ahi[0], H1 + 2);
            mma16816(s0, Ahi[1], H0 + 4); mma16816(s1, Ahi[1], H0 + 6);
            mma16816(s2, Ahi[1], H1 + 4); mma16816(s3, Ahi[1], H1 + 6);
            mma16816(s0, Alo[0], H0 + 0); mma16816(s1, Alo[0], H0 + 2);
            mma16816(s2, Alo[0], H1 + 0); mma16816(s3, Alo[0], H1 + 2);
            mma16816(s0, Alo[1], H0 + 4); mma16816(s1, Alo[1], H0 + 6);
            mma16816(s2, Alo[1], H1 + 4); mma16816(s3, Alo[1], H1 + 6);
        }

        // ---- online softmax ----
        float tm0 = -1e30f, tm1 = -1e30f;
#pragma unroll
        for (int j = 0; j < 8; j++) {
            tm0 = fmaxf(tm0, fmaxf(s[j][0], s[j][1]));
            tm1 = fmaxf(tm1, fmaxf(s[j][2], s[j][3]));
        }
        tm0 = fmaxf(tm0, __shfl_xor_sync(0xffffffffu, tm0, 1));
        tm0 = fmaxf(tm0, __shfl_xor_sync(0xffffffffu, tm0, 2));
        tm1 = fmaxf(tm1, __shfl_xor_sync(0xffffffffu, tm1, 1));
        tm1 = fmaxf(tm1, __shfl_xor_sync(0xffffffffu, tm1, 2));
        float mn0 = fmaxf(m0v, tm0), mn1 = fmaxf(m1v, tm1);
        float c0 = __expf(m0v - mn0), c1 = __expf(m1v - mn1);
        m0v = mn0; m1v = mn1;
        lsum0 *= c0; lsum1 *= c1;
#pragma unroll
        for (int j = 0; j < 4; j++) {
            O[j][0] *= c0; O[j][1] *= c0; O[j][2] *= c1; O[j][3] *= c1;
        }
#pragma unroll
        for (int j = 0; j < 8; j++) {
            s[j][0] = __expf(s[j][0] - mn0); s[j][1] = __expf(s[j][1] - mn0);
            s[j][2] = __expf(s[j][2] - mn1); s[j][3] = __expf(s[j][3] - mn1);
            lsum0 += s[j][0] + s[j][1];
            lsum1 += s[j][2] + s[j][3];
        }

        // ---- O += Phi . vhi : P hi-only, 4-way interleaved ----
#pragma unroll
        for (int c = 0; c < 4; c++) {
            uint32_t Ph[4];
            Ph[0] = hpack(s[2 * c][0], s[2 * c][1]);
            Ph[1] = hpack(s[2 * c][2], s[2 * c][3]);
            Ph[2] = hpack(s[2 * c + 1][0], s[2 * c + 1][1]);
            Ph[3] = hpack(s[2 * c + 1][2], s[2 * c + 1][3]);
            uint32_t v0[4], v1[4];
            uint32_t base = vbase + buf * PANEL + c * 16 * 80;
            ldsm4t(v0[0], v0[1], v0[2], v0[3], base);
            ldsm4t(v1[0], v1[1], v1[2], v1[3], base + 32);
            mma16816(O[0], Ph, v0 + 0); mma16816(O[1], Ph, v0 + 2);
            mma16816(O[2], Ph, v1 + 0); mma16816(O[3], Ph, v1 + 2);
        }
    }
#undef CPKV

    // ---- epilogue ----
    lsum0 += __shfl_xor_sync(0xffffffffu, lsum0, 1);
    lsum0 += __shfl_xor_sync(0xffffffffu, lsum0, 2);
    lsum1 += __shfl_xor_sync(0xffffffffu, lsum1, 1);
    lsum1 += __shfl_xor_sync(0xffffffffu, lsum1, 2);
    float inv0 = 1.f / lsum0, inv1 = 1.f / lsum1;

    __half* baseA = g_attE + (size_t)(b * NT + rowg) * KE2 + h * HD + 2 * qd;
    __half* baseB = baseA + (size_t)8 * KE2;
#pragma unroll
    for (int j = 0; j < 4; j++) {
        int col = j * 8;
        uint32_t hiA = hpack(O[j][0] * inv0, O[j][1] * inv0);
        uint32_t loA = hpack_lo(O[j][0] * inv0, O[j][1] * inv0, hiA);
        *(uint32_t*)(baseA + col)      = hiA;
        *(uint32_t*)(baseA + col + CC) = loA;
        uint32_t hiB = hpack(O[j][2] * inv1, O[j][3] * inv1);
        uint32_t loB = hpack_lo(O[j][2] * inv1, O[j][3] * inv1, hiB);
        *(uint32_t*)(baseB + col)      = hiB;
        *(uint32_t*)(baseB + col + CC) = loB;
    }
}

// ---------------- launch ----------------
extern "C" void kernel_launch(void* const* d_in, const int* in_sizes, int n_in,
                              void* d_out, int out_size) {
    const float* x           = (const float*)d_in[0];
    const float* mask        = (const float*)d_in[1];
    const float* qkv_w       = (const float*)d_in[2];
    const float* q_bias      = (const float*)d_in[3];
    const float* v_bias      = (const float*)d_in[4];
    const float* logit_scale = (const float*)d_in[5];
    const float* cpb_w1      = (const float*)d_in[6];
    const float* cpb_b1      = (const float*)d_in[7];
    const float* cpb_w2      = (const float*)d_in[8];
    const float* proj_w      = (const float*)d_in[9];
    const float* proj_b      = (const float*)d_in[10];
    const float* rel_table   = (const float*)d_in[11];
    const int*   rel_index   = (const int*)d_in[12];
    float* out = (float*)d_out;

    cpb_kernel<<<TBL, 128>>>(rel_table, cpb_w1, cpb_b1, cpb_w2);
    prep_kernel<<<NB_XA + NB_WQ + NB_WP + NB_BF + NB_MF, 256>>>(x, qkv_w, proj_w, rel_index, mask);
    mma_gemm<0><<<dim3(9, 256), 256>>>(q_bias, v_bias, logit_scale, nullptr);
    attn_mma<<<dim3(8, HH, BW), 128>>>();
    mma_gemm<1><<<dim3(3, 256), 256>>>(proj_b, nullptr, nullptr, out);
}

// round 16
// speedup vs baseline: 1.0873x; 1.0032x over previous
#include <cuda_runtime.h>
#include <cuda_fp16.h>
#include <cstdint>

// ---------------- problem constants ----------------
#define BW   64
#define NT   512
#define CC   192
#define HH   6
#define HD   32
#define NWIN 16
#define TBL  3375
#define KE2  384           // expanded K = 2*192 (fp16 hi|lo)

// ---------------- device scratch ----------------
__device__ float g_tbl[TBL * HH];
// bias/mask in mma-fragment layout: [h|w][iblk(8)][warp(4)][jt(8)][j(8)][lane(32)][4]
__device__ float g_biasF[HH * 8 * 4 * 8 * 8 * 32 * 4];      // 6.3 MB
__device__ float g_maskF[NWIN * 8 * 4 * 8 * 8 * 32 * 4];    // 16.8 MB
__device__ float g_q[BW * HH * NT * HD];
// k/v stored as fp16 hi only: 32 halfs (64B) per key
__device__ __half g_kE[(size_t)BW * HH * NT * 32];
__device__ __half g_vE[(size_t)BW * HH * NT * 32];
__device__ __half g_xE[(size_t)BW * NT * KE2];     // x expanded [hi|lo]
__device__ __half g_attE[(size_t)BW * NT * KE2];   // attn out expanded [hi|lo]
__device__ __half g_wqkvE[3 * CC * KE2];           // qkv_w expanded [hi|hi]
__device__ __half g_wprojE[CC * KE2];              // proj_w expanded [hi|hi]

#define SWZ(o) ((o) ^ (((o) >> 3) & 0x70))

__device__ __forceinline__ uint32_t s2u(const void* p) {
    return (uint32_t)__cvta_generic_to_shared(p);
}
__device__ __forceinline__ void ldsm4(uint32_t& r0, uint32_t& r1, uint32_t& r2, uint32_t& r3,
                                      uint32_t addr) {
    asm volatile("ldmatrix.sync.aligned.m8n8.x4.shared.b16 {%0,%1,%2,%3}, [%4];"
                 : "=r"(r0), "=r"(r1), "=r"(r2), "=r"(r3) : "r"(addr));
}
__device__ __forceinline__ void ldsm4t(uint32_t& r0, uint32_t& r1, uint32_t& r2, uint32_t& r3,
                                       uint32_t addr) {
    asm volatile("ldmatrix.sync.aligned.m8n8.x4.trans.shared.b16 {%0,%1,%2,%3}, [%4];"
                 : "=r"(r0), "=r"(r1), "=r"(r2), "=r"(r3) : "r"(addr));
}
__device__ __forceinline__ void mma16816(float* c, const uint32_t* a, const uint32_t* b) {
    asm volatile(
        "mma.sync.aligned.m16n8k16.row.col.f32.f16.f16.f32 "
        "{%0,%1,%2,%3},{%4,%5,%6,%7},{%8,%9},{%0,%1,%2,%3};"
        : "+f"(c[0]), "+f"(c[1]), "+f"(c[2]), "+f"(c[3])
        : "r"(a[0]), "r"(a[1]), "r"(a[2]), "r"(a[3]), "r"(b[0]), "r"(b[1]));
}
__device__ __forceinline__ void cpasync16(uint32_t smem, const void* g) {
    asm volatile("cp.async.cg.shared.global [%0], [%1], 16;" :: "r"(smem), "l"(g));
}
#define CP_COMMIT() asm volatile("cp.async.commit_group;" ::: "memory")
#define CP_WAIT0()  asm volatile("cp.async.wait_group 0;" ::: "memory")

__device__ __forceinline__ uint32_t hpack(float x, float y) {
    __half2 t = __floats2half2_rn(x, y);
    return *(uint32_t*)&t;
}
__device__ __forceinline__ uint32_t hpack_lo(float x, float y, uint32_t hi) {
    __half2 h = *(__half2*)&hi;
    return hpack(x - __half2float(h.x), y - __half2float(h.y));
}

// ---------------- 1. CPB MLP ----------------
__global__ void cpb_kernel(const float* __restrict__ tb, const float* __restrict__ w1,
                           const float* __restrict__ b1, const float* __restrict__ w2) {
    int r = blockIdx.x;
    float c0 = tb[r * 3 + 0], c1 = tb[r * 3 + 1], c2 = tb[r * 3 + 2];
    float acc[HH] = {0.f, 0.f, 0.f, 0.f, 0.f, 0.f};
    for (int j = threadIdx.x; j < 512; j += 128) {
        float hv = fmaf(c0, w1[j * 3 + 0], fmaf(c1, w1[j * 3 + 1], fmaf(c2, w1[j * 3 + 2], b1[j])));
        hv = fmaxf(hv, 0.f);
#pragma unroll
        for (int h = 0; h < HH; h++) acc[h] = fmaf(hv, w2[h * 512 + j], acc[h]);
    }
    __shared__ float red[HH][128];
#pragma unroll
    for (int h = 0; h < HH; h++) red[h][threadIdx.x] = acc[h];
    __syncthreads();
    for (int s = 64; s > 0; s >>= 1) {
        if (threadIdx.x < s) {
#pragma unroll
            for (int h = 0; h < HH; h++) red[h][threadIdx.x] += red[h][threadIdx.x + s];
        }
        __syncthreads();
    }
    if (threadIdx.x < HH) {
        float v = red[threadIdx.x][0];
        g_tbl[r * HH + threadIdx.x] = 16.f / (1.f + __expf(-v));
    }
}

// ---------------- 2. fused prep (expansions + fragment-layout bias/mask) ----------------
#define NB_XA   ((BW * NT * CC) / 256)        // 24576
#define NB_WQ   ((3 * CC * CC) / 256)         // 432
#define NB_WP   ((CC * CC) / 256)             // 144
#define NB_BF   ((HH * 8 * 4 * 8 * 8 * 32) / 256)     // 1536
#define NB_MF   ((NWIN * 8 * 4 * 8 * 8 * 32) / 256)   // 4096
__global__ void prep_kernel(const float* __restrict__ x, const float* __restrict__ qkv_w,
                            const float* __restrict__ proj_w, const int* __restrict__ rel_index,
                            const float* __restrict__ mask) {
    int bid = blockIdx.x;
    if (bid < NB_XA) {
        int i = bid * 256 + threadIdx.x;
        float a = x[i];
        __half hi = __float2half_rn(a);
        __half lo = __float2half_rn(a - __half2float(hi));
        int m = i / CC, k = i - m * CC;
        size_t o = (size_t)m * KE2 + k;
        g_xE[o] = hi; g_xE[o + CC] = lo;
    } else if (bid < NB_XA + NB_WQ) {
        int i = (bid - NB_XA) * 256 + threadIdx.x;
        __half hi = __float2half_rn(qkv_w[i]);
        int n = i / CC, k = i - n * CC;
        size_t o = (size_t)n * KE2 + k;
        g_wqkvE[o] = hi; g_wqkvE[o + CC] = hi;
    } else if (bid < NB_XA + NB_WQ + NB_WP) {
        int i = (bid - NB_XA - NB_WQ) * 256 + threadIdx.x;
        __half hi = __float2half_rn(proj_w[i]);
        int n = i / CC, k = i - n * CC;
        size_t o = (size_t)n * KE2 + k;
        g_wprojE[o] = hi; g_wprojE[o + CC] = hi;
    } else if (bid < NB_XA + NB_WQ + NB_WP + NB_BF) {
        int t = (bid - NB_XA - NB_WQ - NB_WP) * 256 + threadIdx.x;
        int lane = t & 31, j = (t >> 5) & 7, jt = (t >> 8) & 7;
        int wd = (t >> 11) & 3, ib = (t >> 13) & 7, h = t >> 16;
        int row = ib * 64 + wd * 16 + (lane >> 2);
        int col = jt * 64 + j * 8 + (lane & 3) * 2;
        int i0 = rel_index[row * NT + col];
        int i1 = rel_index[row * NT + col + 1];
        int i2 = rel_index[(row + 8) * NT + col];
        int i3 = rel_index[(row + 8) * NT + col + 1];
        float4 v = make_float4(g_tbl[i0 * HH + h], g_tbl[i1 * HH + h],
                               g_tbl[i2 * HH + h], g_tbl[i3 * HH + h]);
        *(float4*)(g_biasF + (size_t)t * 4) = v;
    } else {
        int t = (bid - NB_XA - NB_WQ - NB_WP - NB_BF) * 256 + threadIdx.x;
        int lane = t & 31, j = (t >> 5) & 7, jt = (t >> 8) & 7;
        int wd = (t >> 11) & 3, ib = (t >> 13) & 7, w = t >> 16;
        int row = ib * 64 + wd * 16 + (lane >> 2);
        int col = jt * 64 + j * 8 + (lane & 3) * 2;
        const float* mr0 = mask + ((size_t)w * NT + row) * NT + col;
        const float* mr1 = mask + ((size_t)w * NT + row + 8) * NT + col;
        float4 v = make_float4(mr0[0], mr0[1], mr1[0], mr1[1]);
        *(float4*)(g_maskF + (size_t)t * 4) = v;
    }
}

// ---------------- mma.sync GEMM: block 128(M) x 64(N), K'=384, cp.async 2-stage ----------------
template <int MODE>
__global__ void __launch_bounds__(256) mma_gemm(const float* __restrict__ bq,
                                                const float* __restrict__ bv,
                                                const float* __restrict__ lsc,
                                                float* __restrict__ Cout) {
    __shared__ __align__(128) unsigned char smem_all[49152];

    const int tid = threadIdx.x;
    const int wid = tid >> 5, lane = tid & 31;
    const int wm = wid >> 1, wn = wid & 1;
    const int m0 = blockIdx.y * 128;
    const int n0 = blockIdx.x * 64;

    const __half* AE = (MODE == 0) ? g_xE : g_attE;
    const __half* BE = (MODE == 0) ? g_wqkvE : g_wprojE;

    float acc[2][4][4];
#pragma unroll
    for (int t = 0; t < 2; t++)
#pragma unroll
        for (int nt = 0; nt < 4; nt++)
#pragma unroll
            for (int j = 0; j < 4; j++) acc[t][nt][j] = 0.f;

    const int li = lane & 7, lg = lane >> 3;
    const uint32_t sAu = s2u(smem_all), sBu = s2u(smem_all + 32768);
    const int rowA0 = wm * 32 + li + (lg & 1) * 8;
    const int chA = lg >> 1;
    const int rowB0 = wn * 32 + li + (lg >> 1) * 8;
    const int chB = lg & 1;

    const int grow = tid >> 3, gseg = tid & 7;

#define GSTAGE(c, buf) { \
        uint32_t aB = sAu + (buf) * 16384; \
        uint32_t bB = sBu + (buf) * 8192;  \
        _Pragma("unroll") \
        for (int it = 0; it < 4; it++) { \
            int row = grow + it * 32; \
            cpasync16(aB + SWZ(row * 128 + gseg * 16), \
                      AE + (size_t)(m0 + row) * KE2 + (c) * 64 + gseg * 8); \
        } \
        _Pragma("unroll") \
        for (int it = 0; it < 2; it++) { \
            int row = grow + it * 32; \
            cpasync16(bB + SWZ(row * 128 + gseg * 16), \
                      BE + (size_t)(n0 + row) * KE2 + (c) * 64 + gseg * 8); \
        } \
        CP_COMMIT(); }

    GSTAGE(0, 0);

    for (int c = 0; c < 6; c++) {
        CP_WAIT0();
        __syncthreads();
        if (c < 5) GSTAGE(c + 1, (c + 1) & 1);

        uint32_t aB = sAu + (c & 1) * 16384;
        uint32_t bB = sBu + (c & 1) * 8192;
#pragma unroll
        for (int s = 0; s < 4; s++) {
            uint32_t a[2][4], b[2][4];
#pragma unroll
            for (int t = 0; t < 2; t++) {
                int row = rowA0 + t * 16;
                uint32_t addr = aB + row * 128 + (((2 * s + chA) ^ (row & 7)) << 4);
                ldsm4(a[t][0], a[t][1], a[t][2], a[t][3], addr);
            }
#pragma unroll
            for (int p = 0; p < 2; p++) {
                int row = rowB0 + p * 16;
                uint32_t addr = bB + row * 128 + (((2 * s + chB) ^ (row & 7)) << 4);
                ldsm4(b[p][0], b[p][1], b[p][2], b[p][3], addr);
            }
#pragma unroll
            for (int t = 0; t < 2; t++)
#pragma unroll
                for (int nt = 0; nt < 4; nt++)
                    mma16816(acc[t][nt], a[t], &b[nt >> 1][(nt & 1) * 2]);
        }
    }
#undef GSTAGE

    const int nglob = n0 + wn * 32;
    const int qid = lane & 3;
    if (MODE == 0) {
        const int s = nglob / 192;
        const int rem = nglob - s * 192;
        const int h = rem >> 5;
        float mulq = 0.f;
        if (s == 0) mulq = __expf(fminf(lsc[h], 4.605170186f));
#pragma unroll
        for (int t = 0; t < 2; t++) {
#pragma unroll
            for (int half = 0; half < 2; half++) {
                int mrow = m0 + wm * 32 + t * 16 + half * 8 + (lane >> 2);
                float f[8];
#pragma unroll
                for (int nt = 0; nt < 4; nt++) {
                    int d0 = nt * 8 + qid * 2;
                    float b0 = (s == 0) ? bq[rem + d0] : ((s == 2) ? bv[rem + d0] : 0.f);
                    float b1 = (s == 0) ? bq[rem + d0 + 1] : ((s == 2) ? bv[rem + d0 + 1] : 0.f);
                    f[nt * 2 + 0] = acc[t][nt][half * 2 + 0] + b0;
                    f[nt * 2 + 1] = acc[t][nt][half * 2 + 1] + b1;
                }
                float mul = 1.f;
                if (s < 2) {
                    float ss = 0.f;
#pragma unroll
                    for (int j = 0; j < 8; j++) ss = fmaf(f[j], f[j], ss);
                    ss += __shfl_xor_sync(0xffffffffu, ss, 1);
                    ss += __shfl_xor_sync(0xffffffffu, ss, 2);
                    mul = 1.f / fmaxf(sqrtf(ss), 1e-12f);
                    if (s == 0) mul *= mulq;
                }
                const int bb = mrow >> 9, nr = mrow & 511;
                if (s == 0) {
                    float* op = g_q + ((((size_t)bb * HH + h) << 9) + nr) * HD;
#pragma unroll
                    for (int nt = 0; nt < 4; nt++) {
                        int d0 = nt * 8 + qid * 2;
                        *(float2*)(op + d0) = make_float2(f[nt * 2] * mul, f[nt * 2 + 1] * mul);
                    }
                } else {
                    __half* op = (s == 1 ? g_kE : g_vE) +
                                 ((((size_t)bb * HH + h) << 9) + nr) * 32;
#pragma unroll
                    for (int nt = 0; nt < 4; nt++) {
                        int d0 = nt * 8 + qid * 2;
                        *(uint32_t*)(op + d0) = hpack(f[nt * 2] * mul, f[nt * 2 + 1] * mul);
                    }
                }
            }
        }
    } else {
#pragma unroll
        for (int t = 0; t < 2; t++) {
#pragma unroll
            for (int half = 0; half < 2; half++) {
                int mrow = m0 + wm * 32 + t * 16 + half * 8 + (lane >> 2);
                float* op = Cout + (size_t)mrow * CC + nglob;
#pragma unroll
                for (int nt = 0; nt < 4; nt++) {
                    int d0 = nt * 8 + qid * 2;
                    float pb0 = bq[nglob + d0], pb1 = bq[nglob + d0 + 1];
                    *(float2*)(op + d0) = make_float2(acc[t][nt][half * 2 + 0] + pb0,
                                                      acc[t][nt][half * 2 + 1] + pb1);
                }
            }
        }
    }
}

// ---------------- tensor-core flash attention ----------------
// 128-thread CTA (4 warps x 16 q-rows = 64 rows); 5 CTAs/SM.
// K/V smem panel: 64 keys x 64B (fp16 hi only), row stride 80B.
// Bias/mask from fragment-layout tables (coalesced LDG.128).
// PV uses P-hi only. Row-sum (lsum) computed on the tensor pipe via a
// constant all-ones B fragment (0x3C003C00) — no scalar adds, no shuffles.
#define PANEL 5120
__global__ void __launch_bounds__(128, 5) attn_mma() {
    const int b = blockIdx.z, h = blockIdx.y;
    const int i0 = blockIdx.x * 64;
    const int w = b & (NWIN - 1);
    const int tid = threadIdx.x, wid = tid >> 5, lane = tid & 31;
    const int qd = lane & 3, r = lane >> 2;

    __shared__ __align__(16) unsigned char sK[2 * PANEL];
    __shared__ __align__(16) unsigned char sV[2 * PANEL];
    const uint32_t sKu = s2u(sK), sVu = s2u(sV);

    const __half* kgE = g_kE + (((size_t)(b * HH + h)) << 9) * 32;
    const __half* vgE = g_vE + (((size_t)(b * HH + h)) << 9) * 32;
    const int crow = tid >> 1, chalf = (tid & 1) * 32;

#define CPKV(jt, buf) { \
        const __half* kr = kgE + (size_t)((jt) * 64 + crow) * 32; \
        const __half* vr = vgE + (size_t)((jt) * 64 + crow) * 32; \
        uint32_t kd = sKu + (buf) * PANEL + crow * 80 + chalf; \
        uint32_t vd = sVu + (buf) * PANEL + crow * 80 + chalf; \
        cpasync16(kd,      (const char*)kr + chalf); \
        cpasync16(kd + 16, (const char*)kr + chalf + 16); \
        cpasync16(vd,      (const char*)vr + chalf); \
        cpasync16(vd + 16, (const char*)vr + chalf + 16); \
        CP_COMMIT(); }

    CPKV(0, 0);

    // ---- Q fragments (hi/lo fp16) from fp32 g_q ----
    const int rowg = i0 + wid * 16 + r;
    const float* qrowA = g_q + (((size_t)(b * HH + h) << 9) + rowg) * HD;
    const float* qrowB = qrowA + 8 * HD;
    uint32_t Ahi[2][4], Alo[2][4];
#pragma unroll
    for (int c = 0; c < 2; c++) {
        float2 fa0 = *(const float2*)(qrowA + 2 * qd + 16 * c);
        float2 fb0 = *(const float2*)(qrowB + 2 * qd + 16 * c);
        float2 fa1 = *(const float2*)(qrowA + 2 * qd + 16 * c + 8);
        float2 fb1 = *(const float2*)(qrowB + 2 * qd + 16 * c + 8);
        Ahi[c][0] = hpack(fa0.x, fa0.y); Alo[c][0] = hpack_lo(fa0.x, fa0.y, Ahi[c][0]);
        Ahi[c][1] = hpack(fb0.x, fb0.y); Alo[c][1] = hpack_lo(fb0.x, fb0.y, Ahi[c][1]);
        Ahi[c][2] = hpack(fa1.x, fa1.y); Alo[c][2] = hpack_lo(fa1.x, fa1.y, Ahi[c][2]);
        Ahi[c][3] = hpack(fb1.x, fb1.y); Alo[c][3] = hpack_lo(fb1.x, fb1.y, Ahi[c][3]);
    }

    const int li = lane & 7, lg = lane >> 3;
    const uint32_t kbase = sKu + (((lg >> 1) * 8 + li) * 80) + (lg & 1) * 16;
    const uint32_t vbase = sVu + (((lg & 1) * 8 + li) * 80) + (lg >> 1) * 16;

    const float* pbF = g_biasF + ((size_t)((h * 8 + blockIdx.x) * 4 + wid) * 8) * 1024 + lane * 4;
    const float* pmF = g_maskF + ((size_t)((w * 8 + blockIdx.x) * 4 + wid) * 8) * 1024 + lane * 4;

    const uint32_t onesf[2] = {0x3C003C00u, 0x3C003C00u};   // fp16 1.0 x4

    float O[4][4];
#pragma unroll
    for (int j = 0; j < 4; j++)
#pragma unroll
        for (int u = 0; u < 4; u++) O[j][u] = 0.f;
    float L[4] = {0.f, 0.f, 0.f, 0.f};       // L[0]=rowA sum, L[2]=rowB sum
    float m0v = -1e30f, m1v = -1e30f;

    for (int jt = 0; jt < 8; jt++) {
        const int buf = jt & 1;
        CP_WAIT0();
        __syncthreads();
        if (jt < 7) CPKV(jt + 1, buf ^ 1);

        // ---- init S with bias + mask (coalesced fragment loads) ----
        float s[8][4];
        const float* pbT = pbF + jt * 1024;
        const float* pmT = pmF + jt * 1024;
#pragma unroll
        for (int j = 0; j < 8; j++) {
            float4 bb = *(const float4*)(pbT + j * 128);
            float4 mm = *(const float4*)(pmT + j * 128);
            s[j][0] = bb.x + mm.x; s[j][1] = bb.y + mm.y;
            s[j][2] = bb.z + mm.z; s[j][3] = bb.w + mm.w;
        }

        // ---- S += (qhi+qlo) . khi^T : 2 jp-blocks at a time, 4-way interleaved ----
#pragma unroll
        for (int jph = 0; jph < 2; jph++) {
            uint32_t H0[8], H1[8];
            {
                uint32_t base0 = kbase + buf * PANEL + (2 * jph)     * 16 * 80;
                uint32_t base1 = kbase + buf * PANEL + (2 * jph + 1) * 16 * 80;
                ldsm4(H0[0], H0[1], H0[2], H0[3], base0 + 0);
                ldsm4(H0[4], H0[5], H0[6], H0[7], base0 + 32);
                ldsm4(H1[0], H1[1], H1[2], H1[3], base1 + 0);
                ldsm4(H1[4], H1[5], H1[6], H1[7], base1 + 32);
            }
            float* s0 = s[4 * jph + 0]; float* s1 = s[4 * jph + 1];
            float* s2 = s[4 * jph + 2]; float* s3 = s[4 * jph + 3];
            mma16816(s0, Ahi[0], H0 + 0); mma16816(s1, Ahi[0], H0 + 2);
            mma16816(s2, Ahi[0], H1 + 0); mma16816(s3, Ahi[0], H1 + 2);
            mma16816(s0, Ahi[1], H0 + 4); mma16816(s1, Ahi[1], H0 + 6);
            mma16816(s2, Ahi[1], H1 + 4); mma16816(s3, Ahi[1], H1 + 6);
            mma16816(s0, Alo[0], H0 + 0); mma16816(s1, Alo[0], H0 + 2);
            mma16816(s2, Alo[0], H1 + 0); mma16816(s3, Alo[0], H1 + 2);
            mma16816(s0, Alo[1], H0 + 4); mma16816(s1, Alo[1], H0 + 6);
            mma16816(s2, Alo[1], H1 + 4); mma16816(s3, Alo[1], H1 + 6);
        }

        // ---- online softmax (max only; row sum moves to tensor pipe) ----
        float tm0 = -1e30f, tm1 = -1e30f;
#pragma unroll
        for (int j = 0; j < 8; j++) {
            tm0 = fmaxf(tm0, fmaxf(s[j][0], s[j][1]));
            tm1 = fmaxf(tm1, fmaxf(s[j][2], s[j][3]));
        }
        tm0 = fmaxf(tm0, __shfl_xor_sync(0xffffffffu, tm0, 1));
        tm0 = fmaxf(tm0, __shfl_xor_sync(0xffffffffu, tm0, 2));
        tm1 = fmaxf(tm1, __shfl_xor_sync(0xffffffffu, tm1, 1));
        tm1 = fmaxf(tm1, __shfl_xor_sync(0xffffffffu, tm1, 2));
        float mn0 = fmaxf(m0v, tm0), mn1 = fmaxf(m1v, tm1);
        float c0 = __expf(m0v - mn0), c1 = __expf(m1v - mn1);
        m0v = mn0; m1v = mn1;
#pragma unroll
        for (int j = 0; j < 4; j++) {
            O[j][0] *= c0; O[j][1] *= c0; O[j][2] *= c1; O[j][3] *= c1;
        }
        L[0] *= c0; L[1] *= c0; L[2] *= c1; L[3] *= c1;
#pragma unroll
        for (int j = 0; j < 8; j++) {
            s[j][0] = __expf(s[j][0] - mn0); s[j][1] = __expf(s[j][1] - mn0);
            s[j][2] = __expf(s[j][2] - mn1); s[j][3] = __expf(s[j][3] - mn1);
        }

        // ---- O += Phi . vhi ; L += Phi . ones : 5-way interleaved ----
#pragma unroll
        for (int c = 0; c < 4; c++) {
            uint32_t Ph[4];
            Ph[0] = hpack(s[2 * c][0], s[2 * c][1]);
            Ph[1] = hpack(s[2 * c][2], s[2 * c][3]);
            Ph[2] = hpack(s[2 * c + 1][0], s[2 * c + 1][1]);
            Ph[3] = hpack(s[2 * c + 1][2], s[2 * c + 1][3]);
            uint32_t v0[4], v1[4];
            uint32_t base = vbase + buf * PANEL + c * 16 * 80;
            ldsm4t(v0[0], v0[1], v0[2], v0[3], base);
            ldsm4t(v1[0], v1[1], v1[2], v1[3], base + 32);
            mma16816(O[0], Ph, v0 + 0); mma16816(O[1], Ph, v0 + 2);
            mma16816(O[2], Ph, v1 + 0); mma16816(O[3], Ph, v1 + 2);
            mma16816(L, Ph, onesf);
        }
    }
#undef CPKV

    // ---- epilogue (row sums already in L[0]/L[2], no shuffles) ----
    float inv0 = 1.f / L[0], inv1 = 1.f / L[2];

    __half* baseA = g_attE + (size_t)(b * NT + rowg) * KE2 + h * HD + 2 * qd;
    __half* baseB = baseA + (size_t)8 * KE2;
#pragma unroll
    for (int j = 0; j < 4; j++) {
        int col = j * 8;
        uint32_t hiA = hpack(O[j][0] * inv0, O[j][1] * inv0);
        uint32_t loA = hpack_lo(O[j][0] * inv0, O[j][1] * inv0, hiA);
        *(uint32_t*)(baseA + col)      = hiA;
        *(uint32_t*)(baseA + col + CC) = loA;
        uint32_t hiB = hpack(O[j][2] * inv1, O[j][3] * inv1);
        uint32_t loB = hpack_lo(O[j][2] * inv1, O[j][3] * inv1, hiB);
        *(uint32_t*)(baseB + col)      = hiB;
        *(uint32_t*)(baseB + col + CC) = loB;
    }
}

// ---------------- launch ----------------
extern "C" void kernel_launch(void* const* d_in, const int* in_sizes, int n_in,
                              void* d_out, int out_size) {
    const float* x           = (const float*)d_in[0];
    const float* mask        = (const float*)d_in[1];
    const float* qkv_w       = (const float*)d_in[2];
    const float* q_bias      = (const float*)d_in[3];
    const float* v_bias      = (const float*)d_in[4];
    const float* logit_scale = (const float*)d_in[5];
    const float* cpb_w1      = (const float*)d_in[6];
    const float* cpb_b1      = (const float*)d_in[7];
    const float* cpb_w2      = (const float*)d_in[8];
    const float* proj_w      = (const float*)d_in[9];
    const float* proj_b      = (const float*)d_in[10];
    const float* rel_table   = (const float*)d_in[11];
    const int*   rel_index   = (const int*)d_in[12];
    float* out = (float*)d_out;

    cpb_kernel<<<TBL, 128>>>(rel_table, cpb_w1, cpb_b1, cpb_w2);
    prep_kernel<<<NB_XA + NB_WQ + NB_WP + NB_BF + NB_MF, 256>>>(x, qkv_w, proj_w, rel_index, mask);
    mma_gemm<0><<<dim3(9, 256), 256>>>(q_bias, v_bias, logit_scale, nullptr);
    attn_mma<<<dim3(8, HH, BW), 128>>>();
    mma_gemm<1><<<dim3(3, 256), 256>>>(proj_b, nullptr, nullptr, out);
}

// round 17
// speedup vs baseline: 1.1542x; 1.0615x over previous
#include <cuda_runtime.h>
#include <cuda_fp16.h>
#include <cstdint>

// ---------------- problem constants ----------------
#define BW   64
#define NT   512
#define CC   192
#define HH   6
#define HD   32
#define NWIN 16
#define TBL  3375
#define KE2  384           // expanded K for qkv gemm (fp16 hi|lo)
#define LOG2E 1.4426950408889634f

// ---------------- device scratch ----------------
__device__ float g_tbl[TBL * HH];
// bias/mask in mma-fragment layout, pre-scaled by LOG2E
__device__ float g_biasF[HH * 8 * 4 * 8 * 8 * 32 * 4];      // 6.3 MB
__device__ float g_maskF[NWIN * 8 * 4 * 8 * 8 * 32 * 4];    // 16.8 MB
__device__ float g_q[BW * HH * NT * HD];                    // normalized q * scale * LOG2E
__device__ __half g_kE[(size_t)BW * HH * NT * 32];
__device__ __half g_vE[(size_t)BW * HH * NT * 32];
__device__ __half g_xE[(size_t)BW * NT * KE2];     // x expanded [hi|lo]
__device__ __half g_attE[(size_t)BW * NT * CC];    // attn out fp16 hi only
__device__ __half g_wqkvE[3 * CC * KE2];           // qkv_w expanded [hi|hi]
__device__ __half g_wprojE[CC * CC];               // proj_w fp16 hi only

#define SWZ(o) ((o) ^ (((o) >> 3) & 0x70))

__device__ __forceinline__ uint32_t s2u(const void* p) {
    return (uint32_t)__cvta_generic_to_shared(p);
}
__device__ __forceinline__ void ldsm4(uint32_t& r0, uint32_t& r1, uint32_t& r2, uint32_t& r3,
                                      uint32_t addr) {
    asm volatile("ldmatrix.sync.aligned.m8n8.x4.shared.b16 {%0,%1,%2,%3}, [%4];"
                 : "=r"(r0), "=r"(r1), "=r"(r2), "=r"(r3) : "r"(addr));
}
__device__ __forceinline__ void ldsm4t(uint32_t& r0, uint32_t& r1, uint32_t& r2, uint32_t& r3,
                                       uint32_t addr) {
    asm volatile("ldmatrix.sync.aligned.m8n8.x4.trans.shared.b16 {%0,%1,%2,%3}, [%4];"
                 : "=r"(r0), "=r"(r1), "=r"(r2), "=r"(r3) : "r"(addr));
}
__device__ __forceinline__ void mma16816(float* c, const uint32_t* a, const uint32_t* b) {
    asm volatile(
        "mma.sync.aligned.m16n8k16.row.col.f32.f16.f16.f32 "
        "{%0,%1,%2,%3},{%4,%5,%6,%7},{%8,%9},{%0,%1,%2,%3};"
        : "+f"(c[0]), "+f"(c[1]), "+f"(c[2]), "+f"(c[3])
        : "r"(a[0]), "r"(a[1]), "r"(a[2]), "r"(a[3]), "r"(b[0]), "r"(b[1]));
}
__device__ __forceinline__ void cpasync16(uint32_t smem, const void* g) {
    asm volatile("cp.async.cg.shared.global [%0], [%1], 16;" :: "r"(smem), "l"(g));
}
#define CP_COMMIT() asm volatile("cp.async.commit_group;" ::: "memory")
#define CP_WAIT0()  asm volatile("cp.async.wait_group 0;" ::: "memory")

__device__ __forceinline__ uint32_t hpack(float x, float y) {
    __half2 t = __floats2half2_rn(x, y);
    return *(uint32_t*)&t;
}
__device__ __forceinline__ uint32_t hpack_lo(float x, float y, uint32_t hi) {
    __half2 h = *(__half2*)&hi;
    return hpack(x - __half2float(h.x), y - __half2float(h.y));
}

// ---------------- 1. CPB MLP ----------------
__global__ void cpb_kernel(const float* __restrict__ tb, const float* __restrict__ w1,
                           const float* __restrict__ b1, const float* __restrict__ w2) {
    int r = blockIdx.x;
    float c0 = tb[r * 3 + 0], c1 = tb[r * 3 + 1], c2 = tb[r * 3 + 2];
    float acc[HH] = {0.f, 0.f, 0.f, 0.f, 0.f, 0.f};
    for (int j = threadIdx.x; j < 512; j += 128) {
        float hv = fmaf(c0, w1[j * 3 + 0], fmaf(c1, w1[j * 3 + 1], fmaf(c2, w1[j * 3 + 2], b1[j])));
        hv = fmaxf(hv, 0.f);
#pragma unroll
        for (int h = 0; h < HH; h++) acc[h] = fmaf(hv, w2[h * 512 + j], acc[h]);
    }
    __shared__ float red[HH][128];
#pragma unroll
    for (int h = 0; h < HH; h++) red[h][threadIdx.x] = acc[h];
    __syncthreads();
    for (int s = 64; s > 0; s >>= 1) {
        if (threadIdx.x < s) {
#pragma unroll
            for (int h = 0; h < HH; h++) red[h][threadIdx.x] += red[h][threadIdx.x + s];
        }
        __syncthreads();
    }
    if (threadIdx.x < HH) {
        float v = red[threadIdx.x][0];
        g_tbl[r * HH + threadIdx.x] = 16.f / (1.f + __expf(-v));
    }
}

// ---------------- 2. fused prep ----------------
#define NB_XA   ((BW * NT * CC) / 256)        // 24576
#define NB_WQ   ((3 * CC * CC) / 256)         // 432
#define NB_WP   ((CC * CC) / 256)             // 144
#define NB_BF   ((HH * 8 * 4 * 8 * 8 * 32) / 256)     // 1536
#define NB_MF   ((NWIN * 8 * 4 * 8 * 8 * 32) / 256)   // 4096
__global__ void prep_kernel(const float* __restrict__ x, const float* __restrict__ qkv_w,
                            const float* __restrict__ proj_w, const int* __restrict__ rel_index,
                            const float* __restrict__ mask) {
    int bid = blockIdx.x;
    if (bid < NB_XA) {
        int i = bid * 256 + threadIdx.x;
        float a = x[i];
        __half hi = __float2half_rn(a);
        __half lo = __float2half_rn(a - __half2float(hi));
        int m = i / CC, k = i - m * CC;
        size_t o = (size_t)m * KE2 + k;
        g_xE[o] = hi; g_xE[o + CC] = lo;
    } else if (bid < NB_XA + NB_WQ) {
        int i = (bid - NB_XA) * 256 + threadIdx.x;
        __half hi = __float2half_rn(qkv_w[i]);
        int n = i / CC, k = i - n * CC;
        size_t o = (size_t)n * KE2 + k;
        g_wqkvE[o] = hi; g_wqkvE[o + CC] = hi;
    } else if (bid < NB_XA + NB_WQ + NB_WP) {
        int i = (bid - NB_XA - NB_WQ) * 256 + threadIdx.x;
        g_wprojE[i] = __float2half_rn(proj_w[i]);
    } else if (bid < NB_XA + NB_WQ + NB_WP + NB_BF) {
        int t = (bid - NB_XA - NB_WQ - NB_WP) * 256 + threadIdx.x;
        int lane = t & 31, j = (t >> 5) & 7, jt = (t >> 8) & 7;
        int wd = (t >> 11) & 3, ib = (t >> 13) & 7, h = t >> 16;
        int row = ib * 64 + wd * 16 + (lane >> 2);
        int col = jt * 64 + j * 8 + (lane & 3) * 2;
        int i0 = rel_index[row * NT + col];
        int i1 = rel_index[row * NT + col + 1];
        int i2 = rel_index[(row + 8) * NT + col];
        int i3 = rel_index[(row + 8) * NT + col + 1];
        float4 v = make_float4(g_tbl[i0 * HH + h] * LOG2E, g_tbl[i1 * HH + h] * LOG2E,
                               g_tbl[i2 * HH + h] * LOG2E, g_tbl[i3 * HH + h] * LOG2E);
        *(float4*)(g_biasF + (size_t)t * 4) = v;
    } else {
        int t = (bid - NB_XA - NB_WQ - NB_WP - NB_BF) * 256 + threadIdx.x;
        int lane = t & 31, j = (t >> 5) & 7, jt = (t >> 8) & 7;
        int wd = (t >> 11) & 3, ib = (t >> 13) & 7, w = t >> 16;
        int row = ib * 64 + wd * 16 + (lane >> 2);
        int col = jt * 64 + j * 8 + (lane & 3) * 2;
        const float* mr0 = mask + ((size_t)w * NT + row) * NT + col;
        const float* mr1 = mask + ((size_t)w * NT + row + 8) * NT + col;
        float4 v = make_float4(mr0[0] * LOG2E, mr0[1] * LOG2E,
                               mr1[0] * LOG2E, mr1[1] * LOG2E);
        *(float4*)(g_maskF + (size_t)t * 4) = v;
    }
}

// ---------------- mma.sync GEMM: block 128(M) x 64(N), cp.async 2-stage ----------------
// MODE 0: K'=384 (xE [hi|lo] . wqkvE [hi|hi]); MODE 1: K'=192 (attE hi . wprojE hi).
template <int MODE>
__global__ void __launch_bounds__(256) mma_gemm(const float* __restrict__ bq,
                                                const float* __restrict__ bv,
                                                const float* __restrict__ lsc,
                                                float* __restrict__ Cout) {
    __shared__ __align__(128) unsigned char smem_all[49152];
    const int NCH = (MODE == 0) ? 6 : 3;
    const int KEA = (MODE == 0) ? KE2 : CC;

    const int tid = threadIdx.x;
    const int wid = tid >> 5, lane = tid & 31;
    const int wm = wid >> 1, wn = wid & 1;
    const int m0 = blockIdx.y * 128;
    const int n0 = blockIdx.x * 64;

    const __half* AE = (MODE == 0) ? g_xE : g_attE;
    const __half* BE = (MODE == 0) ? g_wqkvE : g_wprojE;

    float acc[2][4][4];
#pragma unroll
    for (int t = 0; t < 2; t++)
#pragma unroll
        for (int nt = 0; nt < 4; nt++)
#pragma unroll
            for (int j = 0; j < 4; j++) acc[t][nt][j] = 0.f;

    const int li = lane & 7, lg = lane >> 3;
    const uint32_t sAu = s2u(smem_all), sBu = s2u(smem_all + 32768);
    const int rowA0 = wm * 32 + li + (lg & 1) * 8;
    const int chA = lg >> 1;
    const int rowB0 = wn * 32 + li + (lg >> 1) * 8;
    const int chB = lg & 1;

    const int grow = tid >> 3, gseg = tid & 7;

#define GSTAGE(c, buf) { \
        uint32_t aB = sAu + (buf) * 16384; \
        uint32_t bB = sBu + (buf) * 8192;  \
        _Pragma("unroll") \
        for (int it = 0; it < 4; it++) { \
            int row = grow + it * 32; \
            cpasync16(aB + SWZ(row * 128 + gseg * 16), \
                      AE + (size_t)(m0 + row) * KEA + (c) * 64 + gseg * 8); \
        } \
        _Pragma("unroll") \
        for (int it = 0; it < 2; it++) { \
            int row = grow + it * 32; \
            cpasync16(bB + SWZ(row * 128 + gseg * 16), \
                      BE + (size_t)(n0 + row) * KEA + (c) * 64 + gseg * 8); \
        } \
        CP_COMMIT(); }

    GSTAGE(0, 0);

    for (int c = 0; c < NCH; c++) {
        CP_WAIT0();
        __syncthreads();
        if (c < NCH - 1) GSTAGE(c + 1, (c + 1) & 1);

        uint32_t aB = sAu + (c & 1) * 16384;
        uint32_t bB = sBu + (c & 1) * 8192;
#pragma unroll
        for (int s = 0; s < 4; s++) {
            uint32_t a[2][4], b[2][4];
#pragma unroll
            for (int t = 0; t < 2; t++) {
                int row = rowA0 + t * 16;
                uint32_t addr = aB + row * 128 + (((2 * s + chA) ^ (row & 7)) << 4);
                ldsm4(a[t][0], a[t][1], a[t][2], a[t][3], addr);
            }
#pragma unroll
            for (int p = 0; p < 2; p++) {
                int row = rowB0 + p * 16;
                uint32_t addr = bB + row * 128 + (((2 * s + chB) ^ (row & 7)) << 4);
                ldsm4(b[p][0], b[p][1], b[p][2], b[p][3], addr);
            }
#pragma unroll
            for (int t = 0; t < 2; t++)
#pragma unroll
                for (int nt = 0; nt < 4; nt++)
                    mma16816(acc[t][nt], a[t], &b[nt >> 1][(nt & 1) * 2]);
        }
    }
#undef GSTAGE

    const int nglob = n0 + wn * 32;
    const int qid = lane & 3;
    if (MODE == 0) {
        const int s = nglob / 192;
        const int rem = nglob - s * 192;
        const int h = rem >> 5;
        float mulq = 0.f;
        if (s == 0) mulq = __expf(fminf(lsc[h], 4.605170186f)) * LOG2E;
#pragma unroll
        for (int t = 0; t < 2; t++) {
#pragma unroll
            for (int half = 0; half < 2; half++) {
                int mrow = m0 + wm * 32 + t * 16 + half * 8 + (lane >> 2);
                float f[8];
#pragma unroll
                for (int nt = 0; nt < 4; nt++) {
                    int d0 = nt * 8 + qid * 2;
                    float b0 = (s == 0) ? bq[rem + d0] : ((s == 2) ? bv[rem + d0] : 0.f);
                    float b1 = (s == 0) ? bq[rem + d0 + 1] : ((s == 2) ? bv[rem + d0 + 1] : 0.f);
                    f[nt * 2 + 0] = acc[t][nt][half * 2 + 0] + b0;
                    f[nt * 2 + 1] = acc[t][nt][half * 2 + 1] + b1;
                }
                float mul = 1.f;
                if (s < 2) {
                    float ss = 0.f;
#pragma unroll
                    for (int j = 0; j < 8; j++) ss = fmaf(f[j], f[j], ss);
                    ss += __shfl_xor_sync(0xffffffffu, ss, 1);
                    ss += __shfl_xor_sync(0xffffffffu, ss, 2);
                    mul = 1.f / fmaxf(sqrtf(ss), 1e-12f);
                    if (s == 0) mul *= mulq;
                }
                const int bb = mrow >> 9, nr = mrow & 511;
                if (s == 0) {
                    float* op = g_q + ((((size_t)bb * HH + h) << 9) + nr) * HD;
#pragma unroll
                    for (int nt = 0; nt < 4; nt++) {
                        int d0 = nt * 8 + qid * 2;
                        *(float2*)(op + d0) = make_float2(f[nt * 2] * mul, f[nt * 2 + 1] * mul);
                    }
                } else {
                    __half* op = (s == 1 ? g_kE : g_vE) +
                                 ((((size_t)bb * HH + h) << 9) + nr) * 32;
#pragma unroll
                    for (int nt = 0; nt < 4; nt++) {
                        int d0 = nt * 8 + qid * 2;
                        *(uint32_t*)(op + d0) = hpack(f[nt * 2] * mul, f[nt * 2 + 1] * mul);
                    }
                }
            }
        }
    } else {
#pragma unroll
        for (int t = 0; t < 2; t++) {
#pragma unroll
            for (int half = 0; half < 2; half++) {
                int mrow = m0 + wm * 32 + t * 16 + half * 8 + (lane >> 2);
                float* op = Cout + (size_t)mrow * CC + nglob;
#pragma unroll
                for (int nt = 0; nt < 4; nt++) {
                    int d0 = nt * 8 + qid * 2;
                    float pb0 = bq[nglob + d0], pb1 = bq[nglob + d0 + 1];
                    *(float2*)(op + d0) = make_float2(acc[t][nt][half * 2 + 0] + pb0,
                                                      acc[t][nt][half * 2 + 1] + pb1);
                }
            }
        }
    }
}

// ---------------- tensor-core flash attention (exp2 domain) ----------------
#define PANEL 5120
__global__ void __launch_bounds__(128, 5) attn_mma() {
    const int b = blockIdx.z, h = blockIdx.y;
    const int i0 = blockIdx.x * 64;
    const int w = b & (NWIN - 1);
    const int tid = threadIdx.x, wid = tid >> 5, lane = tid & 31;
    const int qd = lane & 3, r = lane >> 2;

    __shared__ __align__(16) unsigned char sK[2 * PANEL];
    __shared__ __align__(16) unsigned char sV[2 * PANEL];
    const uint32_t sKu = s2u(sK), sVu = s2u(sV);

    const __half* kgE = g_kE + (((size_t)(b * HH + h)) << 9) * 32;
    const __half* vgE = g_vE + (((size_t)(b * HH + h)) << 9) * 32;
    const int crow = tid >> 1, chalf = (tid & 1) * 32;

#define CPKV(jt, buf) { \
        const __half* kr = kgE + (size_t)((jt) * 64 + crow) * 32; \
        const __half* vr = vgE + (size_t)((jt) * 64 + crow) * 32; \
        uint32_t kd = sKu + (buf) * PANEL + crow * 80 + chalf; \
        uint32_t vd = sVu + (buf) * PANEL + crow * 80 + chalf; \
        cpasync16(kd,      (const char*)kr + chalf); \
        cpasync16(kd + 16, (const char*)kr + chalf + 16); \
        cpasync16(vd,      (const char*)vr + chalf); \
        cpasync16(vd + 16, (const char*)vr + chalf + 16); \
        CP_COMMIT(); }

    CPKV(0, 0);

    // ---- Q fragments (hi/lo fp16) from fp32 g_q (already *LOG2E) ----
    const int rowg = i0 + wid * 16 + r;
    const float* qrowA = g_q + (((size_t)(b * HH + h) << 9) + rowg) * HD;
    const float* qrowB = qrowA + 8 * HD;
    uint32_t Ahi[2][4], Alo[2][4];
#pragma unroll
    for (int c = 0; c < 2; c++) {
        float2 fa0 = *(const float2*)(qrowA + 2 * qd + 16 * c);
        float2 fb0 = *(const float2*)(qrowB + 2 * qd + 16 * c);
        float2 fa1 = *(const float2*)(qrowA + 2 * qd + 16 * c + 8);
        float2 fb1 = *(const float2*)(qrowB + 2 * qd + 16 * c + 8);
        Ahi[c][0] = hpack(fa0.x, fa0.y); Alo[c][0] = hpack_lo(fa0.x, fa0.y, Ahi[c][0]);
        Ahi[c][1] = hpack(fb0.x, fb0.y); Alo[c][1] = hpack_lo(fb0.x, fb0.y, Ahi[c][1]);
        Ahi[c][2] = hpack(fa1.x, fa1.y); Alo[c][2] = hpack_lo(fa1.x, fa1.y, Ahi[c][2]);
        Ahi[c][3] = hpack(fb1.x, fb1.y); Alo[c][3] = hpack_lo(fb1.x, fb1.y, Ahi[c][3]);
    }

    const int li = lane & 7, lg = lane >> 3;
    const uint32_t kbase = sKu + (((lg >> 1) * 8 + li) * 80) + (lg & 1) * 16;
    const uint32_t vbase = sVu + (((lg & 1) * 8 + li) * 80) + (lg >> 1) * 16;

    const float* pbF = g_biasF + ((size_t)((h * 8 + blockIdx.x) * 4 + wid) * 8) * 1024 + lane * 4;
    const float* pmF = g_maskF + ((size_t)((w * 8 + blockIdx.x) * 4 + wid) * 8) * 1024 + lane * 4;

    const uint32_t onesf[2] = {0x3C003C00u, 0x3C003C00u};   // fp16 1.0 x4

    float O[4][4];
#pragma unroll
    for (int j = 0; j < 4; j++)
#pragma unroll
        for (int u = 0; u < 4; u++) O[j][u] = 0.f;
    float L[4] = {0.f, 0.f, 0.f, 0.f};
    float m0v = -1e30f, m1v = -1e30f;

    for (int jt = 0; jt < 8; jt++) {
        const int buf = jt & 1;
        CP_WAIT0();
        __syncthreads();
        if (jt < 7) CPKV(jt + 1, buf ^ 1);

        // ---- init S with bias + mask (coalesced fragment loads) ----
        float s[8][4];
        const float* pbT = pbF + jt * 1024;
        const float* pmT = pmF + jt * 1024;
#pragma unroll
        for (int j = 0; j < 8; j++) {
            float4 bb = *(const float4*)(pbT + j * 128);
            float4 mm = *(const float4*)(pmT + j * 128);
            s[j][0] = bb.x + mm.x; s[j][1] = bb.y + mm.y;
            s[j][2] = bb.z + mm.z; s[j][3] = bb.w + mm.w;
        }

        // ---- S += (qhi+qlo) . khi^T ----
#pragma unroll
        for (int jph = 0; jph < 2; jph++) {
            uint32_t H0[8], H1[8];
            {
                uint32_t base0 = kbase + buf * PANEL + (2 * jph)     * 16 * 80;
                uint32_t base1 = kbase + buf * PANEL + (2 * jph + 1) * 16 * 80;
                ldsm4(H0[0], H0[1], H0[2], H0[3], base0 + 0);
                ldsm4(H0[4], H0[5], H0[6], H0[7], base0 + 32);
                ldsm4(H1[0], H1[1], H1[2], H1[3], base1 + 0);
                ldsm4(H1[4], H1[5], H1[6], H1[7], base1 + 32);
            }
            float* s0 = s[4 * jph + 0]; float* s1 = s[4 * jph + 1];
            float* s2 = s[4 * jph + 2]; float* s3 = s[4 * jph + 3];
            mma16816(s0, Ahi[0], H0 + 0); mma16816(s1, Ahi[0], H0 + 2);
            mma16816(s2, Ahi[0], H1 + 0); mma16816(s3, Ahi[0], H1 + 2);
            mma16816(s0, Ahi[1], H0 + 4); mma16816(s1, Ahi[1], H0 + 6);
            mma16816(s2, Ahi[1], H1 + 4); mma16816(s3, Ahi[1], H1 + 6);
            mma16816(s0, Alo[0], H0 + 0); mma16816(s1, Alo[0], H0 + 2);
            mma16816(s2, Alo[0], H1 + 0); mma16816(s3, Alo[0], H1 + 2);
            mma16816(s0, Alo[1], H0 + 4); mma16816(s1, Alo[1], H0 + 6);
            mma16816(s2, Alo[1], H1 + 4); mma16816(s3, Alo[1], H1 + 6);
        }

        // ---- online softmax in exp2 domain ----
        float tm0 = -1e30f, tm1 = -1e30f;
#pragma unroll
        for (int j = 0; j < 8; j++) {
            tm0 = fmaxf(tm0, fmaxf(s[j][0], s[j][1]));
            tm1 = fmaxf(tm1, fmaxf(s[j][2], s[j][3]));
        }
        tm0 = fmaxf(tm0, __shfl_xor_sync(0xffffffffu, tm0, 1));
        tm0 = fmaxf(tm0, __shfl_xor_sync(0xffffffffu, tm0, 2));
        tm1 = fmaxf(tm1, __shfl_xor_sync(0xffffffffu, tm1, 1));
        tm1 = fmaxf(tm1, __shfl_xor_sync(0xffffffffu, tm1, 2));
        float mn0 = fmaxf(m0v, tm0), mn1 = fmaxf(m1v, tm1);
        float c0 = exp2f(m0v - mn0), c1 = exp2f(m1v - mn1);
        m0v = mn0; m1v = mn1;
#pragma unroll
        for (int j = 0; j < 4; j++) {
            O[j][0] *= c0; O[j][1] *= c0; O[j][2] *= c1; O[j][3] *= c1;
        }
        L[0] *= c0; L[2] *= c1;
#pragma unroll
        for (int j = 0; j < 8; j++) {
            s[j][0] = exp2f(s[j][0] - mn0); s[j][1] = exp2f(s[j][1] - mn0);
            s[j][2] = exp2f(s[j][2] - mn1); s[j][3] = exp2f(s[j][3] - mn1);
        }

        // ---- O += Phi . vhi ; L += Phi . ones ----
#pragma unroll
        for (int c = 0; c < 4; c++) {
            uint32_t Ph[4];
            Ph[0] = hpack(s[2 * c][0], s[2 * c][1]);
            Ph[1] = hpack(s[2 * c][2], s[2 * c][3]);
            Ph[2] = hpack(s[2 * c + 1][0], s[2 * c + 1][1]);
            Ph[3] = hpack(s[2 * c + 1][2], s[2 * c + 1][3]);
            uint32_t v0[4], v1[4];
            uint32_t base = vbase + buf * PANEL + c * 16 * 80;
            ldsm4t(v0[0], v0[1], v0[2], v0[3], base);
            ldsm4t(v1[0], v1[1], v1[2], v1[3], base + 32);
            mma16816(O[0], Ph, v0 + 0); mma16816(O[1], Ph, v0 + 2);
            mma16816(O[2], Ph, v1 + 0); mma16816(O[3], Ph, v1 + 2);
            mma16816(L, Ph, onesf);
        }
    }
#undef CPKV

    // ---- epilogue: fp16 hi only ----
    float inv0 = 1.f / L[0], inv1 = 1.f / L[2];

    __half* baseA = g_attE + (size_t)(b * NT + rowg) * CC + h * HD + 2 * qd;
    __half* baseB = baseA + (size_t)8 * CC;
#pragma unroll
    for (int j = 0; j < 4; j++) {
        int col = j * 8;
        *(uint32_t*)(baseA + col) = hpack(O[j][0] * inv0, O[j][1] * inv0);
        *(uint32_t*)(baseB + col) = hpack(O[j][2] * inv1, O[j][3] * inv1);
    }
}

// ---------------- launch ----------------
extern "C" void kernel_launch(void* const* d_in, const int* in_sizes, int n_in,
                              void* d_out, int out_size) {
    const float* x           = (const float*)d_in[0];
    const float* mask        = (const float*)d_in[1];
    const float* qkv_w       = (const float*)d_in[2];
    const float* q_bias      = (const float*)d_in[3];
    const float* v_bias      = (const float*)d_in[4];
    const float* logit_scale = (const float*)d_in[5];
    const float* cpb_w1      = (const float*)d_in[6];
    const float* cpb_b1      = (const float*)d_in[7];
    const float* cpb_w2      = (const float*)d_in[8];
    const float* proj_w      = (const float*)d_in[9];
    const float* proj_b      = (const float*)d_in[10];
    const float* rel_table   = (const float*)d_in[11];
    const int*   rel_index   = (const int*)d_in[12];
    float* out = (float*)d_out;

    cpb_kernel<<<TBL, 128>>>(rel_table, cpb_w1, cpb_b1, cpb_w2);
    prep_kernel<<<NB_XA + NB_WQ + NB_WP + NB_BF + NB_MF, 256>>>(x, qkv_w, proj_w, rel_index, mask);
    mma_gemm<0><<<dim3(9, 256), 256>>>(q_bias, v_bias, logit_scale, nullptr);
    attn_mma<<<dim3(8, HH, BW), 128>>>();
    mma_gemm<1><<<dim3(3, 256), 256>>>(proj_b, nullptr, nullptr, out);
}